// round 1
// baseline (speedup 1.0000x reference)
#include <cuda_runtime.h>
#include <cuda_bf16.h>
#include <cstddef>

// ---------------------------------------------------------------------------
// Brain_84301618086488: 4x(conv3x3+BN+ReLU) with 2 maxpools, then 25 per-node
// MLPs (336->600 tanh ->10 softmax) in two stages with neighbor gathering.
// Round-1 design: fold BN, fuse conv1+pool, express conv2/3/4 + MLPs as
// im2col + one tiled fp32 SGEMM. Stage-1 uses Wa[80:336] only (zeros trick);
// stage-2 reuses z1 and only adds nb @ Wa[0:80].
// ---------------------------------------------------------------------------

#define BMAX 8192

// ---- scratch (device globals; no allocation allowed) ----
__device__ float g_pool1 [BMAX * 100 * 64];        // [B,10,10,64] NHWC
__device__ float g_conv2 [BMAX * 100 * 128];       // [B,10,10,128]
__device__ float g_pool2 [BMAX * 25  * 128];       // [B,5,5,128]
__device__ float g_conv3 [BMAX * 25  * 256];       // [B,5,5,256]
__device__ float g_conv4 [BMAX * 25  * 256];       // [B*25,256] rows=(b,pos)
__device__ float g_im2col[471859200];              // max im2col buffer
__device__ float g_z1    [25 * BMAX * 600];        // pre-tanh stage1
__device__ float g_z2    [25 * BMAX * 600];        // pre-tanh stage2
__device__ float g_preds [25 * BMAX * 10];
__device__ float g_second[25 * BMAX * 10];
__device__ float g_nb    [25 * BMAX * 80];
__device__ float g_W1f[64 * 27],    g_b1f[64];
__device__ float g_W2t[576 * 128],  g_b2f[128];
__device__ float g_W3t[1152 * 256], g_b3f[256];
__device__ float g_W4t[2304 * 256], g_b4f[256];
__device__ int   g_nei[25 * 8];

__device__ __forceinline__ float tanh_fast(float x) {
    float y;
    asm("tanh.approx.f32 %0, %1;" : "=f"(y) : "f"(x));
    return y;
}

// ---- fold BN into conv weights, optional transpose to [k*Cin+ci][Co] ----
__global__ void fold_k(const float* __restrict__ W, const float* __restrict__ b,
                       const float* __restrict__ g, const float* __restrict__ be,
                       const float* __restrict__ m, const float* __restrict__ v,
                       float* __restrict__ Wt, float* __restrict__ bt,
                       int Cin, int Co, int transpose) {
    int idx = blockIdx.x * blockDim.x + threadIdx.x;
    int tot = Co * Cin * 9;
    if (idx < tot) {
        int co = idx / (Cin * 9);
        int rem = idx % (Cin * 9);
        int ci = rem / 9, kk = rem % 9;
        float sc = g[co] * rsqrtf(v[co] + 1e-5f);
        float w = W[idx] * sc;
        if (transpose) Wt[(size_t)(kk * Cin + ci) * Co + co] = w;
        else           Wt[idx] = w;
    }
    if (idx < Co) {
        float sc = g[idx] * rsqrtf(v[idx] + 1e-5f);
        bt[idx] = (b[idx] - m[idx]) * sc + be[idx];
    }
}

// ---- neighbor table (matches reference ordering exactly) ----
__global__ void nei_k(int* __restrict__ nei) {
    int i = threadIdx.x;
    if (i >= 25) return;
    const int w = 5, size = 25;
    int n[8]; int c = 0;
    if (i - w >= 0)                          n[c++] = i - w;
    if (i % w != 0)                          n[c++] = i - 1;
    if ((i + 1) % w != 0)                    n[c++] = i + 1;
    if (i + w < size)                        n[c++] = i + w;
    if (i - w - 1 >= 0 && i % w != 0)        n[c++] = i - w - 1;
    if (i - w + 1 >= 0 && (i + 1) % w != 0)  n[c++] = i - w + 1;
    if (i + w - 1 < size && i % w != 0)      n[c++] = i + w - 1;
    if (i + w + 1 < size && (i + 1) % w != 0)n[c++] = i + w + 1;
    while (c < 8) n[c++] = -1;
    for (int j = 0; j < 8; j++) nei[i * 8 + j] = n[j];
}

// ---- conv1 (3->64, 20x20, pad1) + maxpool(3,2,1) -> [B,10,10,64] NHWC ----
__global__ void __launch_bounds__(256) conv1_pool_k(
        const float* __restrict__ x, const float* __restrict__ Wf,
        const float* __restrict__ bf, float* __restrict__ out) {
    __shared__ float sx[1200];    // 3*20*20
    __shared__ float sw[64 * 27];
    __shared__ float sb[64];
    int b = blockIdx.x;
    int tid = threadIdx.x;
    const float* xb = x + (size_t)b * 1200;
    for (int i = tid; i < 1200; i += 256) sx[i] = xb[i];
    for (int i = tid; i < 64 * 27; i += 256) sw[i] = Wf[i];
    if (tid < 64) sb[tid] = bf[tid];
    __syncthreads();
    int co = tid & 63, q = tid >> 6;
    float wr[27];
#pragma unroll
    for (int i = 0; i < 27; i++) wr[i] = sw[co * 27 + i];
    float bias = sb[co];
    for (int p = 0; p < 25; p++) {
        int px = q * 25 + p;
        int oy = px / 10, ox = px % 10;
        float mv = -1e30f;
#pragma unroll
        for (int dy = 0; dy < 3; dy++) {
            int y = 2 * oy - 1 + dy;
            if ((unsigned)y >= 20u) continue;
#pragma unroll
            for (int dx = 0; dx < 3; dx++) {
                int xx = 2 * ox - 1 + dx;
                if ((unsigned)xx >= 20u) continue;
                float s = bias;
#pragma unroll
                for (int ci = 0; ci < 3; ci++)
#pragma unroll
                    for (int ky = 0; ky < 3; ky++) {
                        int iy = y - 1 + ky;
                        if ((unsigned)iy >= 20u) continue;
#pragma unroll
                        for (int kx = 0; kx < 3; kx++) {
                            int ix = xx - 1 + kx;
                            if ((unsigned)ix >= 20u) continue;
                            s += sx[ci * 400 + iy * 20 + ix] * wr[ci * 9 + ky * 3 + kx];
                        }
                    }
                mv = fmaxf(mv, s);
            }
        }
        out[(((size_t)b * 10 + oy) * 10 + ox) * 64 + co] = fmaxf(mv, 0.f);
    }
}

// ---- im2col on NHWC input (3x3 pad1): out[r][(ky*3+kx)*C+ci] ----
__global__ void im2col_k(const float* __restrict__ in, float* __restrict__ out,
                         long long rows, int H, int W, int C) {
    long long idx = (long long)blockIdx.x * blockDim.x + threadIdx.x;
    int c4 = C >> 2;
    long long total = rows * 9 * c4;
    if (idx >= total) return;
    int ci4 = (int)(idx % c4);
    long long t = idx / c4;
    int kk = (int)(t % 9);
    long long r = t / 9;
    int ox = (int)(r % W);
    long long t2 = r / W;
    int oy = (int)(t2 % H);
    long long b = t2 / H;
    int ky = kk / 3, kx = kk % 3;
    int iy = oy + ky - 1, ix = ox + kx - 1;
    float4 v = make_float4(0.f, 0.f, 0.f, 0.f);
    if ((unsigned)iy < (unsigned)H && (unsigned)ix < (unsigned)W)
        v = *(const float4*)&in[(((size_t)b * H + iy) * W + ix) * C + ci4 * 4];
    *(float4*)&out[(size_t)r * (9 * C) + (size_t)kk * C + ci4 * 4] = v;
}

// ---- maxpool 3x3 s2 p1 on NHWC ----
__global__ void pool_nhwc(const float* __restrict__ in, float* __restrict__ out,
                          int Bt, int HI, int WI, int C) {
    int HO = (HI - 1) / 2 + 1;
    long long idx = (long long)blockIdx.x * blockDim.x + threadIdx.x;
    long long total = (long long)Bt * HO * HO * C;
    if (idx >= total) return;
    int c = (int)(idx % C);
    long long t = idx / C;
    int ox = (int)(t % HO); t /= HO;
    int oy = (int)(t % HO);
    long long b = t / HO;
    float mv = -1e30f;
#pragma unroll
    for (int dy = 0; dy < 3; dy++) {
        int y = 2 * oy - 1 + dy;
        if ((unsigned)y >= (unsigned)HI) continue;
#pragma unroll
        for (int dx = 0; dx < 3; dx++) {
            int x2 = 2 * ox - 1 + dx;
            if ((unsigned)x2 >= (unsigned)WI) continue;
            mv = fmaxf(mv, in[(((size_t)b * HI + y) * WI + x2) * C + c]);
        }
    }
    out[idx] = mv;
}

// ---- tiled SGEMM: C[z] = A[z] * B[z] (+bias)(+addsrc)(relu) ----
// BM=BN=128, BK=16, 256 threads, 8x8 per-thread. Requires K%16==0.
__global__ void __launch_bounds__(256) sgemm(
        const float* __restrict__ A, int lda, size_t sA,
        const float* __restrict__ Bm, int ldb, size_t sB,
        float* __restrict__ C, int ldc, size_t sC,
        const float* __restrict__ bias, size_t sBias,
        const float* __restrict__ addsrc, size_t sAdd,
        int M, int N, int K, int epi) {   // epi: 0 none, 1 relu, 2 +=addsrc
    __shared__ float As[16][132];
    __shared__ float Bs[16][132];
    int z = blockIdx.z;
    A += (size_t)z * sA;
    Bm += (size_t)z * sB;
    C += (size_t)z * sC;
    if (bias)   bias   += (size_t)z * sBias;
    if (addsrc) addsrc += (size_t)z * sAdd;
    int m0 = blockIdx.y * 128, n0 = blockIdx.x * 128;
    int tid = threadIdx.x;
    int tx = tid & 15, ty = tid >> 4;
    int arow = tid >> 2;            // 0..63
    int akc = (tid & 3) * 4;        // 0,4,8,12
    int bkr = tid >> 5;             // 0..7
    int bnc = (tid & 31) * 4;       // 0..124
    float acc[8][8];
#pragma unroll
    for (int i = 0; i < 8; i++)
#pragma unroll
        for (int j = 0; j < 8; j++) acc[i][j] = 0.f;

    for (int k0 = 0; k0 < K; k0 += 16) {
#pragma unroll
        for (int h = 0; h < 2; h++) {
            int r = arow + h * 64;
            float4 v = make_float4(0.f, 0.f, 0.f, 0.f);
            int gr = m0 + r;
            if (gr < M) v = *(const float4*)&A[(size_t)gr * lda + k0 + akc];
            As[akc + 0][r] = v.x;
            As[akc + 1][r] = v.y;
            As[akc + 2][r] = v.z;
            As[akc + 3][r] = v.w;
        }
#pragma unroll
        for (int h = 0; h < 2; h++) {
            int kr = bkr + h * 8;
            float4 v = make_float4(0.f, 0.f, 0.f, 0.f);
            if (n0 + bnc < N) v = *(const float4*)&Bm[(size_t)(k0 + kr) * ldb + n0 + bnc];
            *(float4*)&Bs[kr][bnc] = v;
        }
        __syncthreads();
#pragma unroll
        for (int k = 0; k < 16; k++) {
            float ra[8], rb[8];
            *(float4*)&ra[0] = *(const float4*)&As[k][ty * 8];
            *(float4*)&ra[4] = *(const float4*)&As[k][ty * 8 + 4];
            *(float4*)&rb[0] = *(const float4*)&Bs[k][tx * 8];
            *(float4*)&rb[4] = *(const float4*)&Bs[k][tx * 8 + 4];
#pragma unroll
            for (int i = 0; i < 8; i++)
#pragma unroll
                for (int j = 0; j < 8; j++) acc[i][j] += ra[i] * rb[j];
        }
        __syncthreads();
    }
    bool hasBias = (bias != nullptr);
#pragma unroll
    for (int i = 0; i < 8; i++) {
        int row = m0 + ty * 8 + i;
        if (row >= M) continue;
#pragma unroll
        for (int j = 0; j < 8; j++) {
            int col = n0 + tx * 8 + j;
            if (col >= N) continue;
            float v = acc[i][j];
            if (hasBias) v += bias[col];
            if (epi == 1) v = fmaxf(v, 0.f);
            if (epi == 2) v += addsrc[(size_t)row * ldc + col];
            C[(size_t)row * ldc + col] = v;
        }
    }
}

// ---- tanh + Linear(600,10) + softmax; one warp per (node,b) ----
__global__ void __launch_bounds__(256) mlp_out_k(
        const float* __restrict__ z, const float* __restrict__ Wb,
        const float* __restrict__ bb, float* __restrict__ out, int Bt) {
    int n = blockIdx.y;
    int warp = threadIdx.x >> 5, lane = threadIdx.x & 31;
    int b = blockIdx.x * 8 + warp;
    const float* zp = z + ((size_t)n * Bt + b) * 600;
    const float* wb = Wb + (size_t)n * 6000;
    float acc[10];
#pragma unroll
    for (int c = 0; c < 10; c++) acc[c] = 0.f;
    for (int h = lane; h < 600; h += 32) {
        float hv = tanh_fast(zp[h]);
        const float* wr = wb + h * 10;
#pragma unroll
        for (int c = 0; c < 10; c++) acc[c] += hv * wr[c];
    }
#pragma unroll
    for (int c = 0; c < 10; c++)
#pragma unroll
        for (int o = 16; o > 0; o >>= 1)
            acc[c] += __shfl_xor_sync(0xFFFFFFFFu, acc[c], o);
    float logit[10], mx = -1e30f;
#pragma unroll
    for (int c = 0; c < 10; c++) {
        logit[c] = acc[c] + bb[n * 10 + c];
        mx = fmaxf(mx, logit[c]);
    }
    float s = 0.f;
#pragma unroll
    for (int c = 0; c < 10; c++) {
        logit[c] = __expf(logit[c] - mx);
        s += logit[c];
    }
    float inv = 1.f / s;
    if (lane < 10) out[((size_t)n * Bt + b) * 10 + lane] = logit[lane] * inv;
}

// ---- neighbor gather: nb[n][b][j*10+c] ----
__global__ void gather_nb(const float* __restrict__ preds, const int* __restrict__ nei,
                          float* __restrict__ nb, int Bt) {
    long long idx = (long long)blockIdx.x * blockDim.x + threadIdx.x;
    long long total = 25LL * Bt * 80;
    if (idx >= total) return;
    int c = (int)(idx % 10);
    long long t = idx / 10;
    int j = (int)(t % 8); t /= 8;
    int b = (int)(t % Bt);
    int n = (int)(t / Bt);
    int ni = nei[n * 8 + j];
    nb[idx] = (ni >= 0) ? preds[((size_t)ni * Bt + b) * 10 + c] : 0.f;
}

// ---- mean over 25 nodes ----
__global__ void mean_k(const float* __restrict__ second, float* __restrict__ outm, int Bt) {
    int idx = blockIdx.x * blockDim.x + threadIdx.x;
    if (idx >= Bt * 10) return;
    float s = 0.f;
#pragma unroll
    for (int n = 0; n < 25; n++) s += second[(size_t)n * Bt * 10 + idx];
    outm[idx] = s * 0.04f;  // 1/25
}

__global__ void copy_k(const float* __restrict__ src, float* __restrict__ dst, long long n) {
    long long idx = (long long)blockIdx.x * blockDim.x + threadIdx.x;
    if (idx < n) dst[idx] = src[idx];
}

static inline int cdiv(long long a, int b) { return (int)((a + b - 1) / b); }

extern "C" void kernel_launch(void* const* d_in, const int* in_sizes, int n_in,
                              void* d_out, int out_size) {
    const float* x  = (const float*)d_in[0];
    const float* Wc[4], *bc[4], *gc[4], *bec[4], *mc[4], *vc[4];
    for (int l = 0; l < 4; l++) {
        int base = 1 + l * 6;
        Wc[l]  = (const float*)d_in[base + 0];
        bc[l]  = (const float*)d_in[base + 1];
        gc[l]  = (const float*)d_in[base + 2];
        bec[l] = (const float*)d_in[base + 3];
        mc[l]  = (const float*)d_in[base + 4];
        vc[l]  = (const float*)d_in[base + 5];
    }
    const float* Wa = (const float*)d_in[25];
    const float* ba = (const float*)d_in[26];
    const float* Wb = (const float*)d_in[27];
    const float* bb = (const float*)d_in[28];
    int Bt = in_sizes[0] / 1200;  // B*3*20*20 / 1200

    float *p_pool1, *p_conv2, *p_pool2, *p_conv3, *p_conv4, *p_col, *p_z1, *p_z2;
    float *p_preds, *p_second, *p_nb;
    float *p_W1f, *p_b1f, *p_W2t, *p_b2f, *p_W3t, *p_b3f, *p_W4t, *p_b4f;
    int *p_nei;
    cudaGetSymbolAddress((void**)&p_pool1, g_pool1);
    cudaGetSymbolAddress((void**)&p_conv2, g_conv2);
    cudaGetSymbolAddress((void**)&p_pool2, g_pool2);
    cudaGetSymbolAddress((void**)&p_conv3, g_conv3);
    cudaGetSymbolAddress((void**)&p_conv4, g_conv4);
    cudaGetSymbolAddress((void**)&p_col,   g_im2col);
    cudaGetSymbolAddress((void**)&p_z1,    g_z1);
    cudaGetSymbolAddress((void**)&p_z2,    g_z2);
    cudaGetSymbolAddress((void**)&p_preds, g_preds);
    cudaGetSymbolAddress((void**)&p_second,g_second);
    cudaGetSymbolAddress((void**)&p_nb,    g_nb);
    cudaGetSymbolAddress((void**)&p_W1f,   g_W1f);
    cudaGetSymbolAddress((void**)&p_b1f,   g_b1f);
    cudaGetSymbolAddress((void**)&p_W2t,   g_W2t);
    cudaGetSymbolAddress((void**)&p_b2f,   g_b2f);
    cudaGetSymbolAddress((void**)&p_W3t,   g_W3t);
    cudaGetSymbolAddress((void**)&p_b3f,   g_b3f);
    cudaGetSymbolAddress((void**)&p_W4t,   g_W4t);
    cudaGetSymbolAddress((void**)&p_b4f,   g_b4f);
    cudaGetSymbolAddress((void**)&p_nei,   g_nei);

    // fold BN into conv weights
    fold_k<<<cdiv(64 * 27, 256), 256>>>(Wc[0], bc[0], gc[0], bec[0], mc[0], vc[0], p_W1f, p_b1f, 3, 64, 0);
    fold_k<<<cdiv(128 * 576, 256), 256>>>(Wc[1], bc[1], gc[1], bec[1], mc[1], vc[1], p_W2t, p_b2f, 64, 128, 1);
    fold_k<<<cdiv(256 * 1152, 256), 256>>>(Wc[2], bc[2], gc[2], bec[2], mc[2], vc[2], p_W3t, p_b3f, 128, 256, 1);
    fold_k<<<cdiv(256 * 2304, 256), 256>>>(Wc[3], bc[3], gc[3], bec[3], mc[3], vc[3], p_W4t, p_b4f, 256, 256, 1);
    nei_k<<<1, 32>>>(p_nei);

    // conv1 + pool -> [B,10,10,64]
    conv1_pool_k<<<Bt, 256>>>(x, p_W1f, p_b1f, p_pool1);

    // conv2: im2col (K=576) + GEMM -> [B,10,10,128], relu
    long long rows2 = (long long)Bt * 100;
    im2col_k<<<cdiv(rows2 * 9 * 16, 256), 256>>>(p_pool1, p_col, rows2, 10, 10, 64);
    sgemm<<<dim3(1, (unsigned)(rows2 / 128), 1), 256>>>(
        p_col, 576, 0, p_W2t, 128, 0, p_conv2, 128, 0,
        p_b2f, 0, nullptr, 0, (int)rows2, 128, 576, 1);

    // pool2 -> [B,5,5,128]
    pool_nhwc<<<cdiv((long long)Bt * 25 * 128, 256), 256>>>(p_conv2, p_pool2, Bt, 10, 10, 128);

    // conv3: im2col (K=1152) + GEMM -> [B,5,5,256], relu
    long long rows3 = (long long)Bt * 25;
    im2col_k<<<cdiv(rows3 * 9 * 32, 256), 256>>>(p_pool2, p_col, rows3, 5, 5, 128);
    sgemm<<<dim3(2, (unsigned)(rows3 / 128), 1), 256>>>(
        p_col, 1152, 0, p_W3t, 256, 0, p_conv3, 256, 0,
        p_b3f, 0, nullptr, 0, (int)rows3, 256, 1152, 1);

    // conv4: im2col (K=2304) + GEMM -> feats [B*25,256], relu
    im2col_k<<<cdiv(rows3 * 9 * 64, 256), 256>>>(p_conv3, p_col, rows3, 5, 5, 256);
    sgemm<<<dim3(2, (unsigned)(rows3 / 128), 1), 256>>>(
        p_col, 2304, 0, p_W4t, 256, 0, p_conv4, 256, 0,
        p_b4f, 0, nullptr, 0, (int)rows3, 256, 2304, 1);

    // stage1: z1[n] = feats[n] @ Wa[n][80:336] + ba[n]   (pre-tanh, cached)
    sgemm<<<dim3(5, (unsigned)(Bt / 128), 25), 256>>>(
        p_conv4, 25 * 256, 256,                    // A: feats view, stride 256/node
        Wa + 80 * 600, 600, (size_t)336 * 600,     // B: Wa rows 80..335
        p_z1, 600, (size_t)Bt * 600,
        ba, 600, nullptr, 0, Bt, 600, 256, 0);

    // stage1 head: tanh + Linear(600,10) + softmax -> preds
    mlp_out_k<<<dim3(Bt / 8, 25), 256>>>(p_z1, Wb, bb, p_preds, Bt);

    // neighbor gather -> nb [25,B,80]
    gather_nb<<<cdiv(25LL * Bt * 80, 256), 256>>>(p_preds, p_nei, p_nb, Bt);

    // stage2: z2[n] = z1[n] + nb[n] @ Wa[n][0:80]
    sgemm<<<dim3(5, (unsigned)(Bt / 128), 25), 256>>>(
        p_nb, 80, (size_t)Bt * 80,
        Wa, 600, (size_t)336 * 600,
        p_z2, 600, (size_t)Bt * 600,
        nullptr, 0, p_z1, (size_t)Bt * 600, Bt, 600, 80, 2);

    // stage2 head -> second [25,B,10]
    mlp_out_k<<<dim3(Bt / 8, 25), 256>>>(p_z2, Wb, bb, p_second, Bt);

    // outputs: mean [B,10] then second [25,B,10]
    float* outF = (float*)d_out;
    mean_k<<<cdiv(Bt * 10, 256), 256>>>(p_second, outF, Bt);
    long long secN = 25LL * Bt * 10;
    long long room = (long long)out_size - (long long)Bt * 10;
    if (room > 0) {
        long long ncopy = room < secN ? room : secN;
        copy_k<<<cdiv(ncopy, 256), 256>>>(p_second, outF + (size_t)Bt * 10, ncopy);
    }
}

// round 3
// speedup vs baseline: 1.6310x; 1.6310x over previous
#include <cuda_runtime.h>
#include <cstddef>
#include <cstdint>

// ---------------------------------------------------------------------------
// Brain_84301618086488 — round 3: tensor cores via family-portable
// mma.sync.m16n8k8 tf32 (tcgen05 is rejected by the harness's sm_103 PTX
// target). BN folded; conv2/3/4 as implicit-im2col GEMMs; stage-1 MLP uses
// Wa[80:336] (zero-input trick); stage-2 reuses cached z1 and adds
// nb @ Wa[0:80] (K padded to 96).
// ---------------------------------------------------------------------------

#define BMAX 8192

__device__ float g_pool1 [BMAX * 100 * 64];
__device__ float g_conv2 [BMAX * 100 * 128];
__device__ float g_pool2 [BMAX * 25  * 128];
__device__ float g_conv3 [BMAX * 25  * 256];
__device__ float g_conv4 [BMAX * 25  * 256];
__device__ float g_z1    [25 * BMAX * 600];
__device__ float g_z2    [25 * BMAX * 600];
__device__ float g_preds [25 * BMAX * 10];
__device__ float g_second[25 * BMAX * 10];
__device__ float g_nb    [25 * BMAX * 96];
__device__ float g_Wat1  [25 * 600 * 256];   // Wa[80:336]^T per node: [n][k]
__device__ float g_Wat2  [25 * 600 * 96];    // Wa[0:80]^T padded:     [n][k]
__device__ float g_W1f[64 * 27],    g_b1f[64];
__device__ float g_W2f[128 * 576],  g_b2f[128];   // [co][kk*Cin+ci]
__device__ float g_W3f[256 * 1152], g_b3f[256];
__device__ float g_W4f[256 * 2304], g_b4f[256];
__device__ int   g_nei[25 * 8];

__device__ __forceinline__ float tanh_fast(float x) {
    float y; asm("tanh.approx.f32 %0, %1;" : "=f"(y) : "f"(x)); return y;
}
__device__ __forceinline__ float rna_tf32(float x) {
    float y; asm("cvt.rna.tf32.f32 %0, %1;" : "=f"(y) : "f"(x)); return y;
}
__device__ __forceinline__ void mma_tf32(float* d, const uint32_t* a, const uint32_t* b) {
    asm volatile("mma.sync.aligned.m16n8k8.row.col.f32.tf32.tf32.f32 "
                 "{%0,%1,%2,%3}, {%4,%5,%6,%7}, {%8,%9}, {%0,%1,%2,%3};"
                 : "+f"(d[0]), "+f"(d[1]), "+f"(d[2]), "+f"(d[3])
                 : "r"(a[0]), "r"(a[1]), "r"(a[2]), "r"(a[3]), "r"(b[0]), "r"(b[1]));
}

// ---------------------------------------------------------------------------
// Tensor-core GEMM: C[z][m][n] = sum_k A[z][m][k] * B[z][n][k]  (+bias,+add,relu,rna)
// amode 0: A row-major (lda, z-stride sAz elements)
// amode 1: A = implicit im2col of NHWC input (H, Wd, CA channels, 3x3 pad 1)
// M multiple of 128. K multiple of 16. N arbitrary (tile 128).
// epi bits: 1=relu, 2=+addsrc, 4=round result to tf32
// ---------------------------------------------------------------------------
__global__ void __launch_bounds__(256, 1) gemm_mma(
        const float* __restrict__ A, int lda, long long sAz, int amode,
        int H, int Wd, int CA,
        const float* __restrict__ Bw, long long sBz,
        float* __restrict__ Cc, int ldc, long long sCz,
        const float* __restrict__ bias, long long sBiasz,
        const float* __restrict__ addsrc, long long sAddz,
        int N, int K, int epi) {
    __shared__ float As[2][16][132];
    __shared__ float Bs[2][16][132];

    const int tid = threadIdx.x;
    const int wid = tid >> 5, lane = tid & 31;
    const int g = lane >> 2, t4 = lane & 3;
    const int wm = (wid & 1) * 64;      // warp M offset within tile
    const int wn = (wid >> 1) * 32;     // warp N offset within tile
    const int z = blockIdx.z;
    A  += (size_t)z * sAz;
    Bw += (size_t)z * sBz;
    Cc += (size_t)z * sCz;
    if (bias)   bias   += (size_t)z * sBiasz;
    if (addsrc) addsrc += (size_t)z * sAddz;
    const int m0 = blockIdx.y * 128, n0 = blockIdx.x * 128;

    const int arow = tid >> 2;          // 0..63
    const int akc  = (tid & 3) * 4;     // 0,4,8,12
    const int HW = H * Wd;
    const int C = K >> 4;

    float acc[4][4][4];
#pragma unroll
    for (int mi = 0; mi < 4; mi++)
#pragma unroll
        for (int ni = 0; ni < 4; ni++)
#pragma unroll
            for (int q = 0; q < 4; q++) acc[mi][ni][q] = 0.f;

    float4 pa[2], pb[2];

    auto loadA = [&](int c) {
        const int k0 = c * 16;
        if (amode == 0) {
#pragma unroll
            for (int h = 0; h < 2; h++) {
                int r = arow + h * 64;
                pa[h] = __ldg((const float4*)&A[(size_t)(m0 + r) * lda + k0 + akc]);
            }
        } else {
            const int kk = k0 / CA;
            const int ky = kk / 3, kx = kk % 3;
            const int ci = k0 % CA + akc;
#pragma unroll
            for (int h = 0; h < 2; h++) {
                int r = arow + h * 64;
                int m = m0 + r;
                int bimg = m / HW, rem = m % HW;
                int oy = rem / Wd, ox = rem % Wd;
                int iy = oy + ky - 1, ix = ox + kx - 1;
                pa[h] = make_float4(0.f, 0.f, 0.f, 0.f);
                if ((unsigned)iy < (unsigned)H && (unsigned)ix < (unsigned)Wd)
                    pa[h] = __ldg((const float4*)&A[(((size_t)bimg * H + iy) * Wd + ix) * CA + ci]);
            }
        }
    };
    auto loadB = [&](int c) {
        const int k0 = c * 16;
#pragma unroll
        for (int h = 0; h < 2; h++) {
            int r = arow + h * 64;
            pb[h] = (n0 + r < N)
                  ? __ldg((const float4*)&Bw[(size_t)(n0 + r) * K + k0 + akc])
                  : make_float4(0.f, 0.f, 0.f, 0.f);
        }
    };
    auto stage = [&](int buf) {
#pragma unroll
        for (int h = 0; h < 2; h++) {
            int r = arow + h * 64;
            As[buf][akc + 0][r] = pa[h].x;
            As[buf][akc + 1][r] = pa[h].y;
            As[buf][akc + 2][r] = pa[h].z;
            As[buf][akc + 3][r] = pa[h].w;
            Bs[buf][akc + 0][r] = pb[h].x;
            Bs[buf][akc + 1][r] = pb[h].y;
            Bs[buf][akc + 2][r] = pb[h].z;
            Bs[buf][akc + 3][r] = pb[h].w;
        }
    };

    loadA(0); loadB(0);
    stage(0);
    __syncthreads();

    for (int c = 0; c < C; c++) {
        if (c + 1 < C) { loadA(c + 1); loadB(c + 1); }
        const int buf = c & 1;
#pragma unroll
        for (int ks = 0; ks < 2; ks++) {
            const int kb = ks * 8;
            uint32_t afr[4][4], bfr[4][2];
#pragma unroll
            for (int mi = 0; mi < 4; mi++) {
                int m = wm + mi * 16 + g;
                afr[mi][0] = __float_as_uint(As[buf][kb + t4][m]);
                afr[mi][1] = __float_as_uint(As[buf][kb + t4][m + 8]);
                afr[mi][2] = __float_as_uint(As[buf][kb + t4 + 4][m]);
                afr[mi][3] = __float_as_uint(As[buf][kb + t4 + 4][m + 8]);
            }
#pragma unroll
            for (int ni = 0; ni < 4; ni++) {
                int n = wn + ni * 8 + g;
                bfr[ni][0] = __float_as_uint(Bs[buf][kb + t4][n]);
                bfr[ni][1] = __float_as_uint(Bs[buf][kb + t4 + 4][n]);
            }
#pragma unroll
            for (int mi = 0; mi < 4; mi++)
#pragma unroll
                for (int ni = 0; ni < 4; ni++)
                    mma_tf32(acc[mi][ni], afr[mi], bfr[ni]);
        }
        if (c + 1 < C) stage((c + 1) & 1);
        __syncthreads();
    }

    // ---- epilogue ----
#pragma unroll
    for (int mi = 0; mi < 4; mi++) {
        int row0 = m0 + wm + mi * 16 + g;
#pragma unroll
        for (int ni = 0; ni < 4; ni++) {
            int col = n0 + wn + ni * 8 + 2 * t4;
            if (col >= N) continue;
            float b0 = 0.f, b1 = 0.f;
            if (bias) { b0 = __ldg(&bias[col]); b1 = __ldg(&bias[col + 1]); }
#pragma unroll
            for (int hh = 0; hh < 2; hh++) {
                int row = row0 + hh * 8;
                float v0 = acc[mi][ni][hh * 2 + 0] + b0;
                float v1 = acc[mi][ni][hh * 2 + 1] + b1;
                if (epi & 2) {
                    const float2 a2 = *(const float2*)&addsrc[(size_t)row * ldc + col];
                    v0 += a2.x; v1 += a2.y;
                }
                if (epi & 1) { v0 = fmaxf(v0, 0.f); v1 = fmaxf(v1, 0.f); }
                if (epi & 4) { v0 = rna_tf32(v0); v1 = rna_tf32(v1); }
                *(float2*)&Cc[(size_t)row * ldc + col] = make_float2(v0, v1);
            }
        }
    }
}

// --------------------- prep kernels -----------------------------------------
__global__ void fold_k(const float* __restrict__ W, const float* __restrict__ b,
                       const float* __restrict__ g, const float* __restrict__ be,
                       const float* __restrict__ m, const float* __restrict__ v,
                       float* __restrict__ Wt, float* __restrict__ bt,
                       int Cin, int Co, int mode) {
    int idx = blockIdx.x * blockDim.x + threadIdx.x;
    int tot = Co * Cin * 9;
    if (idx < tot) {
        int co = idx / (Cin * 9);
        int rem = idx % (Cin * 9);
        int ci = rem / 9, kk = rem % 9;
        float sc = g[co] * rsqrtf(v[co] + 1e-5f);
        float w = W[idx] * sc;
        if (mode) Wt[(size_t)co * (Cin * 9) + kk * Cin + ci] = rna_tf32(w);
        else      Wt[idx] = w;
    }
    if (idx < Co) {
        float sc = g[idx] * rsqrtf(v[idx] + 1e-5f);
        bt[idx] = (b[idx] - m[idx]) * sc + be[idx];
    }
}

__global__ void wat_k(const float* __restrict__ Wa, float* __restrict__ w1,
                      float* __restrict__ w2) {
    long long idx = (long long)blockIdx.x * blockDim.x + threadIdx.x;
    if (idx < 25LL * 600 * 256) {
        int k = (int)(idx % 256); long long t = idx / 256;
        int j = (int)(t % 600);   int n = (int)(t / 600);
        w1[idx] = rna_tf32(Wa[(size_t)n * 201600 + (size_t)(80 + k) * 600 + j]);
    }
    if (idx < 25LL * 600 * 96) {
        int k = (int)(idx % 96); long long t = idx / 96;
        int j = (int)(t % 600);  int n = (int)(t / 600);
        w2[idx] = (k < 80) ? rna_tf32(Wa[(size_t)n * 201600 + (size_t)k * 600 + j]) : 0.f;
    }
}

__global__ void nei_k(int* __restrict__ nei) {
    int i = threadIdx.x;
    if (i >= 25) return;
    const int w = 5, size = 25;
    int n[8]; int c = 0;
    if (i - w >= 0)                           n[c++] = i - w;
    if (i % w != 0)                           n[c++] = i - 1;
    if ((i + 1) % w != 0)                     n[c++] = i + 1;
    if (i + w < size)                         n[c++] = i + w;
    if (i - w - 1 >= 0 && i % w != 0)         n[c++] = i - w - 1;
    if (i - w + 1 >= 0 && (i + 1) % w != 0)   n[c++] = i - w + 1;
    if (i + w - 1 < size && i % w != 0)       n[c++] = i + w - 1;
    if (i + w + 1 < size && (i + 1) % w != 0) n[c++] = i + w + 1;
    while (c < 8) n[c++] = -1;
    for (int j = 0; j < 8; j++) nei[i * 8 + j] = n[j];
}

__global__ void __launch_bounds__(256) conv1_pool_k(
        const float* __restrict__ x, const float* __restrict__ Wf,
        const float* __restrict__ bf, float* __restrict__ out) {
    __shared__ float sx[1200];
    __shared__ float sw[64 * 27];
    __shared__ float sb2[64];
    int b = blockIdx.x;
    int tid = threadIdx.x;
    const float* xb = x + (size_t)b * 1200;
    for (int i = tid; i < 1200; i += 256) sx[i] = xb[i];
    for (int i = tid; i < 64 * 27; i += 256) sw[i] = Wf[i];
    if (tid < 64) sb2[tid] = bf[tid];
    __syncthreads();
    int co = tid & 63, q = tid >> 6;
    float wr[27];
#pragma unroll
    for (int i = 0; i < 27; i++) wr[i] = sw[co * 27 + i];
    float bias = sb2[co];
    for (int p = 0; p < 25; p++) {
        int px = q * 25 + p;
        int oy = px / 10, ox = px % 10;
        float mv = -1e30f;
#pragma unroll
        for (int dy = 0; dy < 3; dy++) {
            int y = 2 * oy - 1 + dy;
            if ((unsigned)y >= 20u) continue;
#pragma unroll
            for (int dx = 0; dx < 3; dx++) {
                int xx = 2 * ox - 1 + dx;
                if ((unsigned)xx >= 20u) continue;
                float s = bias;
#pragma unroll
                for (int ci = 0; ci < 3; ci++)
#pragma unroll
                    for (int ky = 0; ky < 3; ky++) {
                        int iy = y - 1 + ky;
                        if ((unsigned)iy >= 20u) continue;
#pragma unroll
                        for (int kx = 0; kx < 3; kx++) {
                            int ix = xx - 1 + kx;
                            if ((unsigned)ix >= 20u) continue;
                            s += sx[ci * 400 + iy * 20 + ix] * wr[ci * 9 + ky * 3 + kx];
                        }
                    }
                mv = fmaxf(mv, s);
            }
        }
        out[(((size_t)b * 10 + oy) * 10 + ox) * 64 + co] = rna_tf32(fmaxf(mv, 0.f));
    }
}

__global__ void pool_nhwc(const float* __restrict__ in, float* __restrict__ out,
                          int Bt, int HI, int WI, int Ch) {
    int HO = (HI - 1) / 2 + 1;
    long long idx = (long long)blockIdx.x * blockDim.x + threadIdx.x;
    long long total = (long long)Bt * HO * HO * Ch;
    if (idx >= total) return;
    int c = (int)(idx % Ch);
    long long t = idx / Ch;
    int ox = (int)(t % HO); t /= HO;
    int oy = (int)(t % HO);
    long long b = t / HO;
    float mv = -1e30f;
#pragma unroll
    for (int dy = 0; dy < 3; dy++) {
        int y = 2 * oy - 1 + dy;
        if ((unsigned)y >= (unsigned)HI) continue;
#pragma unroll
        for (int dx = 0; dx < 3; dx++) {
            int x2 = 2 * ox - 1 + dx;
            if ((unsigned)x2 >= (unsigned)WI) continue;
            mv = fmaxf(mv, in[(((size_t)b * HI + y) * WI + x2) * Ch + c]);
        }
    }
    out[idx] = mv;
}

// tanh + Linear(600,10) + softmax; Wb cached in smem
__global__ void __launch_bounds__(256) mlp_out_k(
        const float* __restrict__ z, const float* __restrict__ Wb,
        const float* __restrict__ bb, float* __restrict__ out, int Bt) {
    __shared__ float sW[600 * 11];
    __shared__ float sbb[16];
    int n = blockIdx.y;
    const float* wsrc = Wb + (size_t)n * 6000;
    for (int i = threadIdx.x; i < 6000; i += 256)
        sW[(i / 10) * 11 + (i % 10)] = wsrc[i];
    if (threadIdx.x < 10) sbb[threadIdx.x] = bb[n * 10 + threadIdx.x];
    __syncthreads();
    int warp = threadIdx.x >> 5, lane = threadIdx.x & 31;
    for (int it = 0; it < 4; it++) {
        int b = blockIdx.x * 32 + warp * 4 + it;
        const float* zp = z + ((size_t)n * Bt + b) * 600;
        float acc[10];
#pragma unroll
        for (int c = 0; c < 10; c++) acc[c] = 0.f;
        for (int h = lane; h < 600; h += 32) {
            float hv = tanh_fast(zp[h]);
            const float* wr = &sW[h * 11];
#pragma unroll
            for (int c = 0; c < 10; c++) acc[c] += hv * wr[c];
        }
#pragma unroll
        for (int c = 0; c < 10; c++)
#pragma unroll
            for (int o = 16; o > 0; o >>= 1)
                acc[c] += __shfl_xor_sync(0xFFFFFFFFu, acc[c], o);
        float logit[10], mx = -1e30f;
#pragma unroll
        for (int c = 0; c < 10; c++) {
            logit[c] = acc[c] + sbb[c];
            mx = fmaxf(mx, logit[c]);
        }
        float s = 0.f;
#pragma unroll
        for (int c = 0; c < 10; c++) { logit[c] = __expf(logit[c] - mx); s += logit[c]; }
        float inv = 1.f / s;
        if (lane < 10) out[((size_t)n * Bt + b) * 10 + lane] = logit[lane] * inv;
    }
}

__global__ void gather_nb(const float* __restrict__ preds, const int* __restrict__ nei,
                          float* __restrict__ nb, int Bt) {
    long long idx = (long long)blockIdx.x * blockDim.x + threadIdx.x;
    long long total = 25LL * Bt * 96;
    if (idx >= total) return;
    int c = (int)(idx % 96);
    long long t = idx / 96;
    int b = (int)(t % Bt);
    int n = (int)(t / Bt);
    float v = 0.f;
    if (c < 80) {
        int j = c / 10, cc = c % 10;
        int ni = nei[n * 8 + j];
        if (ni >= 0) v = preds[((size_t)ni * Bt + b) * 10 + cc];
    }
    nb[idx] = rna_tf32(v);
}

__global__ void mean_k(const float* __restrict__ second, float* __restrict__ outm, int Bt) {
    int idx = blockIdx.x * blockDim.x + threadIdx.x;
    if (idx >= Bt * 10) return;
    float s = 0.f;
#pragma unroll
    for (int n = 0; n < 25; n++) s += second[(size_t)n * Bt * 10 + idx];
    outm[idx] = s * 0.04f;
}

__global__ void copy_k(const float* __restrict__ src, float* __restrict__ dst, long long n) {
    long long idx = (long long)blockIdx.x * blockDim.x + threadIdx.x;
    if (idx < n) dst[idx] = src[idx];
}

static inline int cdiv(long long a, int b) { return (int)((a + b - 1) / b); }

extern "C" void kernel_launch(void* const* d_in, const int* in_sizes, int n_in,
                              void* d_out, int out_size) {
    const float* x = (const float*)d_in[0];
    const float *Wc[4], *bc[4], *gc[4], *bec[4], *mc[4], *vc[4];
    for (int l = 0; l < 4; l++) {
        int base = 1 + l * 6;
        Wc[l] = (const float*)d_in[base + 0];
        bc[l] = (const float*)d_in[base + 1];
        gc[l] = (const float*)d_in[base + 2];
        bec[l] = (const float*)d_in[base + 3];
        mc[l] = (const float*)d_in[base + 4];
        vc[l] = (const float*)d_in[base + 5];
    }
    const float* Wa = (const float*)d_in[25];
    const float* ba = (const float*)d_in[26];
    const float* Wb = (const float*)d_in[27];
    const float* bb = (const float*)d_in[28];
    int Bt = in_sizes[0] / 1200;

    float *p_pool1, *p_conv2, *p_pool2, *p_conv3, *p_conv4, *p_z1, *p_z2;
    float *p_preds, *p_second, *p_nb, *p_Wat1, *p_Wat2;
    float *p_W1f, *p_b1f, *p_W2f, *p_b2f, *p_W3f, *p_b3f, *p_W4f, *p_b4f;
    int* p_nei;
    cudaGetSymbolAddress((void**)&p_pool1, g_pool1);
    cudaGetSymbolAddress((void**)&p_conv2, g_conv2);
    cudaGetSymbolAddress((void**)&p_pool2, g_pool2);
    cudaGetSymbolAddress((void**)&p_conv3, g_conv3);
    cudaGetSymbolAddress((void**)&p_conv4, g_conv4);
    cudaGetSymbolAddress((void**)&p_z1, g_z1);
    cudaGetSymbolAddress((void**)&p_z2, g_z2);
    cudaGetSymbolAddress((void**)&p_preds, g_preds);
    cudaGetSymbolAddress((void**)&p_second, g_second);
    cudaGetSymbolAddress((void**)&p_nb, g_nb);
    cudaGetSymbolAddress((void**)&p_Wat1, g_Wat1);
    cudaGetSymbolAddress((void**)&p_Wat2, g_Wat2);
    cudaGetSymbolAddress((void**)&p_W1f, g_W1f);
    cudaGetSymbolAddress((void**)&p_b1f, g_b1f);
    cudaGetSymbolAddress((void**)&p_W2f, g_W2f);
    cudaGetSymbolAddress((void**)&p_b2f, g_b2f);
    cudaGetSymbolAddress((void**)&p_W3f, g_W3f);
    cudaGetSymbolAddress((void**)&p_b3f, g_b3f);
    cudaGetSymbolAddress((void**)&p_W4f, g_W4f);
    cudaGetSymbolAddress((void**)&p_b4f, g_b4f);
    cudaGetSymbolAddress((void**)&p_nei, g_nei);

    // prep (folded weights, transposed MLP weights, neighbor table)
    fold_k<<<cdiv(64 * 27, 256), 256>>>(Wc[0], bc[0], gc[0], bec[0], mc[0], vc[0], p_W1f, p_b1f, 3, 64, 0);
    fold_k<<<cdiv(128 * 576, 256), 256>>>(Wc[1], bc[1], gc[1], bec[1], mc[1], vc[1], p_W2f, p_b2f, 64, 128, 1);
    fold_k<<<cdiv(256 * 1152, 256), 256>>>(Wc[2], bc[2], gc[2], bec[2], mc[2], vc[2], p_W3f, p_b3f, 128, 256, 1);
    fold_k<<<cdiv(256 * 2304, 256), 256>>>(Wc[3], bc[3], gc[3], bec[3], mc[3], vc[3], p_W4f, p_b4f, 256, 256, 1);
    wat_k<<<cdiv(25LL * 600 * 256, 256), 256>>>(Wa, p_Wat1, p_Wat2);
    nei_k<<<1, 32>>>(p_nei);

    // conv1 + pool -> [B,10,10,64] (tf32-rounded)
    conv1_pool_k<<<Bt, 256>>>(x, p_W1f, p_b1f, p_pool1);

    long long rows2 = (long long)Bt * 100;
    long long rows3 = (long long)Bt * 25;

    // conv2: implicit GEMM, K=576, N=128
    gemm_mma<<<dim3(1, (unsigned)(rows2 / 128), 1), 256>>>(
        p_pool1, 0, 0, 1, 10, 10, 64,
        p_W2f, 0, p_conv2, 128, 0,
        p_b2f, 0, nullptr, 0, 128, 576, 1 | 4);

    pool_nhwc<<<cdiv((long long)Bt * 25 * 128, 256), 256>>>(p_conv2, p_pool2, Bt, 10, 10, 128);

    // conv3: K=1152, N=256
    gemm_mma<<<dim3(2, (unsigned)(rows3 / 128), 1), 256>>>(
        p_pool2, 0, 0, 1, 5, 5, 128,
        p_W3f, 0, p_conv3, 256, 0,
        p_b3f, 0, nullptr, 0, 256, 1152, 1 | 4);

    // conv4: K=2304, N=256 -> feats [B*25,256]
    gemm_mma<<<dim3(2, (unsigned)(rows3 / 128), 1), 256>>>(
        p_conv3, 0, 0, 1, 5, 5, 256,
        p_W4f, 0, p_conv4, 256, 0,
        p_b4f, 0, nullptr, 0, 256, 2304, 1 | 4);

    // stage1: z1[n] = feats[n] @ Wa[n][80:336]^T + ba[n]  (K=256, N=600)
    gemm_mma<<<dim3(5, (unsigned)(Bt / 128), 25), 256>>>(
        p_conv4, 25 * 256, 256, 0, 0, 0, 0,
        p_Wat1, 600LL * 256, p_z1, 600, (long long)Bt * 600,
        ba, 600, nullptr, 0, 600, 256, 0);

    mlp_out_k<<<dim3(Bt / 32, 25), 256>>>(p_z1, Wb, bb, p_preds, Bt);

    gather_nb<<<cdiv(25LL * Bt * 96, 256), 256>>>(p_preds, p_nei, p_nb, Bt);

    // stage2: z2[n] = z1[n] + nb[n] @ Wa[n][0:80]^T  (K=96 padded, N=600)
    gemm_mma<<<dim3(5, (unsigned)(Bt / 128), 25), 256>>>(
        p_nb, 96, (long long)Bt * 96, 0, 0, 0, 0,
        p_Wat2, 600LL * 96, p_z2, 600, (long long)Bt * 600,
        nullptr, 0, p_z1, (long long)Bt * 600, 600, 96, 2);

    mlp_out_k<<<dim3(Bt / 32, 25), 256>>>(p_z2, Wb, bb, p_second, Bt);

    float* outF = (float*)d_out;
    mean_k<<<cdiv(Bt * 10, 256), 256>>>(p_second, outF, Bt);
    long long secN = 25LL * Bt * 10;
    long long room = (long long)out_size - (long long)Bt * 10;
    if (room > 0) {
        long long ncopy = room < secN ? room : secN;
        copy_k<<<cdiv(ncopy, 256), 256>>>(p_second, outF + (size_t)Bt * 10, ncopy);
    }
}

// round 4
// speedup vs baseline: 1.8181x; 1.1147x over previous
#include <cuda_runtime.h>
#include <cstddef>
#include <cstdint>

// ---------------------------------------------------------------------------
// Brain_84301618086488 — round 4: mma.sync tf32 GEMM rebuilt around
// cp.async (zfill) -> [row][20]-stride smem (conflict-free fragment LDS),
// 4-stage pipeline. Same algebra as R3: BN folded, implicit-im2col convs,
// stage-1 zeros trick (K=256), stage-2 z1 reuse (K=96).
// ---------------------------------------------------------------------------

#define BMAX 8192
#define ST 4           // pipeline stages
#define RS 20          // smem row stride in floats (16 data + 4 pad)

__device__ float g_pool1 [BMAX * 100 * 64];
__device__ float g_conv2 [BMAX * 100 * 128];
__device__ float g_pool2 [BMAX * 25  * 128];
__device__ float g_conv3 [BMAX * 25  * 256];
__device__ float g_conv4 [BMAX * 25  * 256];
__device__ float g_z1    [25 * BMAX * 600];
__device__ float g_z2    [25 * BMAX * 600];
__device__ float g_preds [25 * BMAX * 10];
__device__ float g_second[25 * BMAX * 10];
__device__ float g_nb    [25 * BMAX * 96];
__device__ float g_Wat1  [25 * 600 * 256];
__device__ float g_Wat2  [25 * 600 * 96];
__device__ float g_W1f[64 * 27],    g_b1f[64];
__device__ float g_W2f[128 * 576],  g_b2f[128];
__device__ float g_W3f[256 * 1152], g_b3f[256];
__device__ float g_W4f[256 * 2304], g_b4f[256];
__device__ int   g_nei[25 * 8];

__device__ __forceinline__ float tanh_fast(float x) {
    float y; asm("tanh.approx.f32 %0, %1;" : "=f"(y) : "f"(x)); return y;
}
__device__ __forceinline__ float rna_tf32(float x) {
    float y; asm("cvt.rna.tf32.f32 %0, %1;" : "=f"(y) : "f"(x)); return y;
}
__device__ __forceinline__ void mma_tf32(float* d, const uint32_t* a, const uint32_t* b) {
    asm volatile("mma.sync.aligned.m16n8k8.row.col.f32.tf32.tf32.f32 "
                 "{%0,%1,%2,%3}, {%4,%5,%6,%7}, {%8,%9}, {%0,%1,%2,%3};"
                 : "+f"(d[0]), "+f"(d[1]), "+f"(d[2]), "+f"(d[3])
                 : "r"(a[0]), "r"(a[1]), "r"(a[2]), "r"(a[3]), "r"(b[0]), "r"(b[1]));
}
__device__ __forceinline__ uint32_t smem_u32(const void* p) {
    uint32_t a;
    asm("{ .reg .u64 t; cvta.to.shared.u64 t, %1; cvt.u32.u64 %0, t; }" : "=r"(a) : "l"(p));
    return a;
}
__device__ __forceinline__ void cp16(uint32_t dst, const void* src, int sz) {
    asm volatile("cp.async.ca.shared.global [%0], [%1], 16, %2;"
                 :: "r"(dst), "l"(src), "r"(sz) : "memory");
}
__device__ __forceinline__ void cp_commit() {
    asm volatile("cp.async.commit_group;" ::: "memory");
}

// ---------------------------------------------------------------------------
// C[z][m][n] = sum_k A[z][m][k]*B[z][n][k]  (+bias,+addsrc,relu,rna)
// amode 0: A row-major; amode 1: implicit im2col 3x3 pad1 over NHWC (H,Wd,CA).
// M % 128 == 0, K % 16 == 0, N arbitrary (tile 128). epi: 1=relu 2=add 4=rna.
// smem: As[ST][128][RS], Bs[ST][128][RS] floats (dynamic, 81920 B).
// ---------------------------------------------------------------------------
__global__ void __launch_bounds__(256, 1) gemm_mma(
        const float* __restrict__ A, int lda, long long sAz, int amode,
        int H, int Wd, int CA,
        const float* __restrict__ Bw, long long sBz,
        float* __restrict__ Cc, int ldc, long long sCz,
        const float* __restrict__ bias, long long sBiasz,
        const float* __restrict__ addsrc, long long sAddz,
        int N, int K, int epi) {
    extern __shared__ float sm[];
    float* Asm = sm;                    // ST*128*RS
    float* Bsm = sm + ST * 128 * RS;
    const uint32_t sA0 = smem_u32(Asm);
    const uint32_t sB0 = smem_u32(Bsm);

    const int tid = threadIdx.x;
    const int wid = tid >> 5, lane = tid & 31;
    const int g = lane >> 2, t4 = lane & 3;
    const int wm = (wid & 1) * 64;
    const int wn = (wid >> 1) * 32;
    const int z = blockIdx.z;
    A  += (size_t)z * sAz;
    Bw += (size_t)z * sBz;
    Cc += (size_t)z * sCz;
    if (bias)   bias   += (size_t)z * sBiasz;
    if (addsrc) addsrc += (size_t)z * sAddz;
    const int m0 = blockIdx.y * 128, n0 = blockIdx.x * 128;
    const int HW = H * Wd;
    const int C = K >> 4;

    // per-thread cp.async coordinates: 2 chunks of 16B per tile
    const int r0 = tid >> 2;            // 0..63
    const int c4 = (tid & 3) * 4;       // 0,4,8,12

    auto issue = [&](int c) {
        const int stage = c & (ST - 1);
        const int k0 = c * 16;
        const uint32_t aBase = sA0 + (uint32_t)(stage * 128 * RS) * 4;
        const uint32_t bBase = sB0 + (uint32_t)(stage * 128 * RS) * 4;
        // A tile
        if (amode == 0) {
#pragma unroll
            for (int h = 0; h < 2; h++) {
                int r = r0 + h * 64;
                cp16(aBase + (uint32_t)(r * RS + c4) * 4,
                     &A[(size_t)(m0 + r) * lda + k0 + c4], 16);
            }
        } else {
            const int kk = k0 / CA;
            const int ky = kk / 3, kx = kk % 3;
            const int ci = k0 % CA + c4;
#pragma unroll
            for (int h = 0; h < 2; h++) {
                int r = r0 + h * 64;
                int m = m0 + r;
                int bimg = m / HW, rem = m % HW;
                int oy = rem / Wd, ox = rem % Wd;
                int iy = oy + ky - 1, ix = ox + kx - 1;
                bool ok = (unsigned)iy < (unsigned)H && (unsigned)ix < (unsigned)Wd;
                const float* src = ok
                    ? &A[(((size_t)bimg * H + iy) * Wd + ix) * CA + ci] : A;
                cp16(aBase + (uint32_t)(r * RS + c4) * 4, src, ok ? 16 : 0);
            }
        }
        // B tile
#pragma unroll
        for (int h = 0; h < 2; h++) {
            int r = r0 + h * 64;
            bool ok = (n0 + r) < N;
            const float* src = ok ? &Bw[(size_t)(n0 + r) * K + k0 + c4] : Bw;
            cp16(bBase + (uint32_t)(r * RS + c4) * 4, src, ok ? 16 : 0);
        }
    };

    float acc[4][4][4];
#pragma unroll
    for (int mi = 0; mi < 4; mi++)
#pragma unroll
        for (int ni = 0; ni < 4; ni++)
#pragma unroll
            for (int q = 0; q < 4; q++) acc[mi][ni][q] = 0.f;

    // prologue: stages 0..ST-2
#pragma unroll
    for (int s = 0; s < ST - 1; s++) {
        if (s < C) issue(s);
        cp_commit();
    }

    for (int c = 0; c < C; c++) {
        asm volatile("cp.async.wait_group %0;" :: "n"(ST - 2) : "memory");
        __syncthreads();
        if (c + ST - 1 < C) issue(c + ST - 1);
        cp_commit();

        const int stage = c & (ST - 1);
        const float* Ab = Asm + stage * 128 * RS;
        const float* Bb = Bsm + stage * 128 * RS;
#pragma unroll
        for (int ks = 0; ks < 2; ks++) {
            const int kb = ks * 8;
            uint32_t afr[4][4], bfr[4][2];
#pragma unroll
            for (int mi = 0; mi < 4; mi++) {
                int m = wm + mi * 16 + g;
                afr[mi][0] = __float_as_uint(Ab[m * RS + kb + t4]);
                afr[mi][1] = __float_as_uint(Ab[(m + 8) * RS + kb + t4]);
                afr[mi][2] = __float_as_uint(Ab[m * RS + kb + t4 + 4]);
                afr[mi][3] = __float_as_uint(Ab[(m + 8) * RS + kb + t4 + 4]);
            }
#pragma unroll
            for (int ni = 0; ni < 4; ni++) {
                int n = wn + ni * 8 + g;
                bfr[ni][0] = __float_as_uint(Bb[n * RS + kb + t4]);
                bfr[ni][1] = __float_as_uint(Bb[n * RS + kb + t4 + 4]);
            }
#pragma unroll
            for (int mi = 0; mi < 4; mi++)
#pragma unroll
                for (int ni = 0; ni < 4; ni++)
                    mma_tf32(acc[mi][ni], afr[mi], bfr[ni]);
        }
        __syncthreads();
    }
    asm volatile("cp.async.wait_group 0;" ::: "memory");

    // ---- epilogue ----
#pragma unroll
    for (int mi = 0; mi < 4; mi++) {
        int row0 = m0 + wm + mi * 16 + g;
#pragma unroll
        for (int ni = 0; ni < 4; ni++) {
            int col = n0 + wn + ni * 8 + 2 * t4;
            if (col >= N) continue;
            float b0 = 0.f, b1 = 0.f;
            if (bias) { b0 = __ldg(&bias[col]); b1 = __ldg(&bias[col + 1]); }
#pragma unroll
            for (int hh = 0; hh < 2; hh++) {
                int row = row0 + hh * 8;
                float v0 = acc[mi][ni][hh * 2 + 0] + b0;
                float v1 = acc[mi][ni][hh * 2 + 1] + b1;
                if (epi & 2) {
                    const float2 a2 = *(const float2*)&addsrc[(size_t)row * ldc + col];
                    v0 += a2.x; v1 += a2.y;
                }
                if (epi & 1) { v0 = fmaxf(v0, 0.f); v1 = fmaxf(v1, 0.f); }
                if (epi & 4) { v0 = rna_tf32(v0); v1 = rna_tf32(v1); }
                *(float2*)&Cc[(size_t)row * ldc + col] = make_float2(v0, v1);
            }
        }
    }
}

// --------------------- prep / small kernels ---------------------------------
__global__ void fold_k(const float* __restrict__ W, const float* __restrict__ b,
                       const float* __restrict__ g, const float* __restrict__ be,
                       const float* __restrict__ m, const float* __restrict__ v,
                       float* __restrict__ Wt, float* __restrict__ bt,
                       int Cin, int Co, int mode) {
    int idx = blockIdx.x * blockDim.x + threadIdx.x;
    int tot = Co * Cin * 9;
    if (idx < tot) {
        int co = idx / (Cin * 9);
        int rem = idx % (Cin * 9);
        int ci = rem / 9, kk = rem % 9;
        float sc = g[co] * rsqrtf(v[co] + 1e-5f);
        float w = W[idx] * sc;
        if (mode) Wt[(size_t)co * (Cin * 9) + kk * Cin + ci] = rna_tf32(w);
        else      Wt[idx] = w;
    }
    if (idx < Co) {
        float sc = g[idx] * rsqrtf(v[idx] + 1e-5f);
        bt[idx] = (b[idx] - m[idx]) * sc + be[idx];
    }
}

__global__ void wat_k(const float* __restrict__ Wa, float* __restrict__ w1,
                      float* __restrict__ w2) {
    long long idx = (long long)blockIdx.x * blockDim.x + threadIdx.x;
    if (idx < 25LL * 600 * 256) {
        int k = (int)(idx % 256); long long t = idx / 256;
        int j = (int)(t % 600);   int n = (int)(t / 600);
        w1[idx] = rna_tf32(Wa[(size_t)n * 201600 + (size_t)(80 + k) * 600 + j]);
    }
    if (idx < 25LL * 600 * 96) {
        int k = (int)(idx % 96); long long t = idx / 96;
        int j = (int)(t % 600);  int n = (int)(t / 600);
        w2[idx] = (k < 80) ? rna_tf32(Wa[(size_t)n * 201600 + (size_t)k * 600 + j]) : 0.f;
    }
}

__global__ void nei_k(int* __restrict__ nei) {
    int i = threadIdx.x;
    if (i >= 25) return;
    const int w = 5, size = 25;
    int n[8]; int c = 0;
    if (i - w >= 0)                           n[c++] = i - w;
    if (i % w != 0)                           n[c++] = i - 1;
    if ((i + 1) % w != 0)                     n[c++] = i + 1;
    if (i + w < size)                         n[c++] = i + w;
    if (i - w - 1 >= 0 && i % w != 0)         n[c++] = i - w - 1;
    if (i - w + 1 >= 0 && (i + 1) % w != 0)   n[c++] = i - w + 1;
    if (i + w - 1 < size && i % w != 0)       n[c++] = i + w - 1;
    if (i + w + 1 < size && (i + 1) % w != 0) n[c++] = i + w + 1;
    while (c < 8) n[c++] = -1;
    for (int j = 0; j < 8; j++) nei[i * 8 + j] = n[j];
}

__global__ void __launch_bounds__(256) conv1_pool_k(
        const float* __restrict__ x, const float* __restrict__ Wf,
        const float* __restrict__ bf, float* __restrict__ out) {
    __shared__ float sx[1200];
    __shared__ float sw[64 * 27];
    __shared__ float sb2[64];
    int b = blockIdx.x;
    int tid = threadIdx.x;
    const float* xb = x + (size_t)b * 1200;
    for (int i = tid; i < 1200; i += 256) sx[i] = xb[i];
    for (int i = tid; i < 64 * 27; i += 256) sw[i] = Wf[i];
    if (tid < 64) sb2[tid] = bf[tid];
    __syncthreads();
    int co = tid & 63, q = tid >> 6;
    float wr[27];
#pragma unroll
    for (int i = 0; i < 27; i++) wr[i] = sw[co * 27 + i];
    float bias = sb2[co];
    for (int p = 0; p < 25; p++) {
        int px = q * 25 + p;
        int oy = px / 10, ox = px % 10;
        float mv = -1e30f;
#pragma unroll
        for (int dy = 0; dy < 3; dy++) {
            int y = 2 * oy - 1 + dy;
            if ((unsigned)y >= 20u) continue;
#pragma unroll
            for (int dx = 0; dx < 3; dx++) {
                int xx = 2 * ox - 1 + dx;
                if ((unsigned)xx >= 20u) continue;
                float s = bias;
#pragma unroll
                for (int ci = 0; ci < 3; ci++)
#pragma unroll
                    for (int ky = 0; ky < 3; ky++) {
                        int iy = y - 1 + ky;
                        if ((unsigned)iy >= 20u) continue;
#pragma unroll
                        for (int kx = 0; kx < 3; kx++) {
                            int ix = xx - 1 + kx;
                            if ((unsigned)ix >= 20u) continue;
                            s += sx[ci * 400 + iy * 20 + ix] * wr[ci * 9 + ky * 3 + kx];
                        }
                    }
                mv = fmaxf(mv, s);
            }
        }
        out[(((size_t)b * 10 + oy) * 10 + ox) * 64 + co] = rna_tf32(fmaxf(mv, 0.f));
    }
}

__global__ void pool_nhwc(const float* __restrict__ in, float* __restrict__ out,
                          int Bt, int HI, int WI, int Ch) {
    int HO = (HI - 1) / 2 + 1;
    long long idx = (long long)blockIdx.x * blockDim.x + threadIdx.x;
    long long total = (long long)Bt * HO * HO * Ch;
    if (idx >= total) return;
    int c = (int)(idx % Ch);
    long long t = idx / Ch;
    int ox = (int)(t % HO); t /= HO;
    int oy = (int)(t % HO);
    long long b = t / HO;
    float mv = -1e30f;
#pragma unroll
    for (int dy = 0; dy < 3; dy++) {
        int y = 2 * oy - 1 + dy;
        if ((unsigned)y >= (unsigned)HI) continue;
#pragma unroll
        for (int dx = 0; dx < 3; dx++) {
            int x2 = 2 * ox - 1 + dx;
            if ((unsigned)x2 >= (unsigned)WI) continue;
            mv = fmaxf(mv, in[(((size_t)b * HI + y) * WI + x2) * Ch + c]);
        }
    }
    out[idx] = mv;
}

__global__ void __launch_bounds__(256) mlp_out_k(
        const float* __restrict__ z, const float* __restrict__ Wb,
        const float* __restrict__ bb, float* __restrict__ out, int Bt) {
    __shared__ float sW[600 * 11];
    __shared__ float sbb[16];
    int n = blockIdx.y;
    const float* wsrc = Wb + (size_t)n * 6000;
    for (int i = threadIdx.x; i < 6000; i += 256)
        sW[(i / 10) * 11 + (i % 10)] = wsrc[i];
    if (threadIdx.x < 10) sbb[threadIdx.x] = bb[n * 10 + threadIdx.x];
    __syncthreads();
    int warp = threadIdx.x >> 5, lane = threadIdx.x & 31;
    for (int it = 0; it < 4; it++) {
        int b = blockIdx.x * 32 + warp * 4 + it;
        const float* zp = z + ((size_t)n * Bt + b) * 600;
        float acc[10];
#pragma unroll
        for (int c = 0; c < 10; c++) acc[c] = 0.f;
        for (int h = lane; h < 600; h += 32) {
            float hv = tanh_fast(zp[h]);
            const float* wr = &sW[h * 11];
#pragma unroll
            for (int c = 0; c < 10; c++) acc[c] += hv * wr[c];
        }
#pragma unroll
        for (int c = 0; c < 10; c++)
#pragma unroll
            for (int o = 16; o > 0; o >>= 1)
                acc[c] += __shfl_xor_sync(0xFFFFFFFFu, acc[c], o);
        float logit[10], mx = -1e30f;
#pragma unroll
        for (int c = 0; c < 10; c++) {
            logit[c] = acc[c] + sbb[c];
            mx = fmaxf(mx, logit[c]);
        }
        float s = 0.f;
#pragma unroll
        for (int c = 0; c < 10; c++) { logit[c] = __expf(logit[c] - mx); s += logit[c]; }
        float inv = 1.f / s;
        if (lane < 10) out[((size_t)n * Bt + b) * 10 + lane] = logit[lane] * inv;
    }
}

__global__ void gather_nb(const float* __restrict__ preds, const int* __restrict__ nei,
                          float* __restrict__ nb, int Bt) {
    long long idx = (long long)blockIdx.x * blockDim.x + threadIdx.x;
    long long total = 25LL * Bt * 96;
    if (idx >= total) return;
    int c = (int)(idx % 96);
    long long t = idx / 96;
    int b = (int)(t % Bt);
    int n = (int)(t / Bt);
    float v = 0.f;
    if (c < 80) {
        int j = c / 10, cc = c % 10;
        int ni = nei[n * 8 + j];
        if (ni >= 0) v = preds[((size_t)ni * Bt + b) * 10 + cc];
    }
    nb[idx] = rna_tf32(v);
}

__global__ void mean_k(const float* __restrict__ second, float* __restrict__ outm, int Bt) {
    int idx = blockIdx.x * blockDim.x + threadIdx.x;
    if (idx >= Bt * 10) return;
    float s = 0.f;
#pragma unroll
    for (int n = 0; n < 25; n++) s += second[(size_t)n * Bt * 10 + idx];
    outm[idx] = s * 0.04f;
}

__global__ void copy_k(const float* __restrict__ src, float* __restrict__ dst, long long n) {
    long long idx = (long long)blockIdx.x * blockDim.x + threadIdx.x;
    if (idx < n) dst[idx] = src[idx];
}

static inline int cdiv(long long a, int b) { return (int)((a + b - 1) / b); }

extern "C" void kernel_launch(void* const* d_in, const int* in_sizes, int n_in,
                              void* d_out, int out_size) {
    const float* x = (const float*)d_in[0];
    const float *Wc[4], *bc[4], *gc[4], *bec[4], *mc[4], *vc[4];
    for (int l = 0; l < 4; l++) {
        int base = 1 + l * 6;
        Wc[l] = (const float*)d_in[base + 0];
        bc[l] = (const float*)d_in[base + 1];
        gc[l] = (const float*)d_in[base + 2];
        bec[l] = (const float*)d_in[base + 3];
        mc[l] = (const float*)d_in[base + 4];
        vc[l] = (const float*)d_in[base + 5];
    }
    const float* Wa = (const float*)d_in[25];
    const float* ba = (const float*)d_in[26];
    const float* Wb = (const float*)d_in[27];
    const float* bb = (const float*)d_in[28];
    int Bt = in_sizes[0] / 1200;

    float *p_pool1, *p_conv2, *p_pool2, *p_conv3, *p_conv4, *p_z1, *p_z2;
    float *p_preds, *p_second, *p_nb, *p_Wat1, *p_Wat2;
    float *p_W1f, *p_b1f, *p_W2f, *p_b2f, *p_W3f, *p_b3f, *p_W4f, *p_b4f;
    int* p_nei;
    cudaGetSymbolAddress((void**)&p_pool1, g_pool1);
    cudaGetSymbolAddress((void**)&p_conv2, g_conv2);
    cudaGetSymbolAddress((void**)&p_pool2, g_pool2);
    cudaGetSymbolAddress((void**)&p_conv3, g_conv3);
    cudaGetSymbolAddress((void**)&p_conv4, g_conv4);
    cudaGetSymbolAddress((void**)&p_z1, g_z1);
    cudaGetSymbolAddress((void**)&p_z2, g_z2);
    cudaGetSymbolAddress((void**)&p_preds, g_preds);
    cudaGetSymbolAddress((void**)&p_second, g_second);
    cudaGetSymbolAddress((void**)&p_nb, g_nb);
    cudaGetSymbolAddress((void**)&p_Wat1, g_Wat1);
    cudaGetSymbolAddress((void**)&p_Wat2, g_Wat2);
    cudaGetSymbolAddress((void**)&p_W1f, g_W1f);
    cudaGetSymbolAddress((void**)&p_b1f, g_b1f);
    cudaGetSymbolAddress((void**)&p_W2f, g_W2f);
    cudaGetSymbolAddress((void**)&p_b2f, g_b2f);
    cudaGetSymbolAddress((void**)&p_W3f, g_W3f);
    cudaGetSymbolAddress((void**)&p_b3f, g_b3f);
    cudaGetSymbolAddress((void**)&p_W4f, g_W4f);
    cudaGetSymbolAddress((void**)&p_b4f, g_b4f);
    cudaGetSymbolAddress((void**)&p_nei, g_nei);

    const int SMEM = 2 * ST * 128 * RS * 4;   // 81920 bytes
    cudaFuncSetAttribute(gemm_mma, cudaFuncAttributeMaxDynamicSharedMemorySize, SMEM);

    fold_k<<<cdiv(64 * 27, 256), 256>>>(Wc[0], bc[0], gc[0], bec[0], mc[0], vc[0], p_W1f, p_b1f, 3, 64, 0);
    fold_k<<<cdiv(128 * 576, 256), 256>>>(Wc[1], bc[1], gc[1], bec[1], mc[1], vc[1], p_W2f, p_b2f, 64, 128, 1);
    fold_k<<<cdiv(256 * 1152, 256), 256>>>(Wc[2], bc[2], gc[2], bec[2], mc[2], vc[2], p_W3f, p_b3f, 128, 256, 1);
    fold_k<<<cdiv(256 * 2304, 256), 256>>>(Wc[3], bc[3], gc[3], bec[3], mc[3], vc[3], p_W4f, p_b4f, 256, 256, 1);
    wat_k<<<cdiv(25LL * 600 * 256, 256), 256>>>(Wa, p_Wat1, p_Wat2);
    nei_k<<<1, 32>>>(p_nei);

    conv1_pool_k<<<Bt, 256>>>(x, p_W1f, p_b1f, p_pool1);

    long long rows2 = (long long)Bt * 100;
    long long rows3 = (long long)Bt * 25;

    // conv2: implicit GEMM, K=576, N=128
    gemm_mma<<<dim3(1, (unsigned)(rows2 / 128), 1), 256, SMEM>>>(
        p_pool1, 0, 0, 1, 10, 10, 64,
        p_W2f, 0, p_conv2, 128, 0,
        p_b2f, 0, nullptr, 0, 128, 576, 1 | 4);

    pool_nhwc<<<cdiv((long long)Bt * 25 * 128, 256), 256>>>(p_conv2, p_pool2, Bt, 10, 10, 128);

    // conv3: K=1152, N=256
    gemm_mma<<<dim3(2, (unsigned)(rows3 / 128), 1), 256, SMEM>>>(
        p_pool2, 0, 0, 1, 5, 5, 128,
        p_W3f, 0, p_conv3, 256, 0,
        p_b3f, 0, nullptr, 0, 256, 1152, 1 | 4);

    // conv4: K=2304, N=256
    gemm_mma<<<dim3(2, (unsigned)(rows3 / 128), 1), 256, SMEM>>>(
        p_conv3, 0, 0, 1, 5, 5, 256,
        p_W4f, 0, p_conv4, 256, 0,
        p_b4f, 0, nullptr, 0, 256, 2304, 1 | 4);

    // stage1: K=256, N=600
    gemm_mma<<<dim3(5, (unsigned)(Bt / 128), 25), 256, SMEM>>>(
        p_conv4, 25 * 256, 256, 0, 0, 0, 0,
        p_Wat1, 600LL * 256, p_z1, 600, (long long)Bt * 600,
        ba, 600, nullptr, 0, 600, 256, 0);

    mlp_out_k<<<dim3(Bt / 32, 25), 256>>>(p_z1, Wb, bb, p_preds, Bt);

    gather_nb<<<cdiv(25LL * Bt * 96, 256), 256>>>(p_preds, p_nei, p_nb, Bt);

    // stage2: K=96, N=600, z2 = z1 + nb@Wat2
    gemm_mma<<<dim3(5, (unsigned)(Bt / 128), 25), 256, SMEM>>>(
        p_nb, 96, (long long)Bt * 96, 0, 0, 0, 0,
        p_Wat2, 600LL * 96, p_z2, 600, (long long)Bt * 600,
        nullptr, 0, p_z1, (long long)Bt * 600, 600, 96, 2);

    mlp_out_k<<<dim3(Bt / 32, 25), 256>>>(p_z2, Wb, bb, p_second, Bt);

    float* outF = (float*)d_out;
    mean_k<<<cdiv(Bt * 10, 256), 256>>>(p_second, outF, Bt);
    long long secN = 25LL * Bt * 10;
    long long room = (long long)out_size - (long long)Bt * 10;
    if (room > 0) {
        long long ncopy = room < secN ? room : secN;
        copy_k<<<cdiv(ncopy, 256), 256>>>(p_second, outF + (size_t)Bt * 10, ncopy);
    }
}

// round 5
// speedup vs baseline: 2.0333x; 1.1183x over previous
#include <cuda_runtime.h>
#include <cstddef>
#include <cstdint>

// ---------------------------------------------------------------------------
// Brain_84301618086488 — round 5: mma.sync tf32, CTA tile 256x128 (warp tile
// 64x64, 8 warps), cp.async 4-stage pipeline, [row][20] conflict-free smem.
// Algebra unchanged: BN folded, implicit-im2col convs, stage-1 zeros trick,
// stage-2 z1 reuse.
// ---------------------------------------------------------------------------

#define BMAX 8192
#define ST 4           // pipeline stages
#define RS 20          // smem row stride in floats (16 data + 4 pad)
#define BM 256
#define BN 128

__device__ float g_pool1 [BMAX * 100 * 64];
__device__ float g_conv2 [BMAX * 100 * 128];
__device__ float g_pool2 [BMAX * 25  * 128];
__device__ float g_conv3 [BMAX * 25  * 256];
__device__ float g_conv4 [BMAX * 25  * 256];
__device__ float g_z1    [25 * BMAX * 600];
__device__ float g_z2    [25 * BMAX * 600];
__device__ float g_preds [25 * BMAX * 10];
__device__ float g_second[25 * BMAX * 10];
__device__ float g_nb    [25 * BMAX * 96];
__device__ float g_Wat1  [25 * 600 * 256];
__device__ float g_Wat2  [25 * 600 * 96];
__device__ float g_W1f[64 * 27],    g_b1f[64];
__device__ float g_W2f[128 * 576],  g_b2f[128];
__device__ float g_W3f[256 * 1152], g_b3f[256];
__device__ float g_W4f[256 * 2304], g_b4f[256];
__device__ int   g_nei[25 * 8];

__device__ __forceinline__ float tanh_fast(float x) {
    float y; asm("tanh.approx.f32 %0, %1;" : "=f"(y) : "f"(x)); return y;
}
__device__ __forceinline__ float rna_tf32(float x) {
    float y; asm("cvt.rna.tf32.f32 %0, %1;" : "=f"(y) : "f"(x)); return y;
}
__device__ __forceinline__ void mma_tf32(float* d, const uint32_t* a, const uint32_t* b) {
    asm volatile("mma.sync.aligned.m16n8k8.row.col.f32.tf32.tf32.f32 "
                 "{%0,%1,%2,%3}, {%4,%5,%6,%7}, {%8,%9}, {%0,%1,%2,%3};"
                 : "+f"(d[0]), "+f"(d[1]), "+f"(d[2]), "+f"(d[3])
                 : "r"(a[0]), "r"(a[1]), "r"(a[2]), "r"(a[3]), "r"(b[0]), "r"(b[1]));
}
__device__ __forceinline__ uint32_t smem_u32(const void* p) {
    uint32_t a;
    asm("{ .reg .u64 t; cvta.to.shared.u64 t, %1; cvt.u32.u64 %0, t; }" : "=r"(a) : "l"(p));
    return a;
}
__device__ __forceinline__ void cp16(uint32_t dst, const void* src, int sz) {
    asm volatile("cp.async.ca.shared.global [%0], [%1], 16, %2;"
                 :: "r"(dst), "l"(src), "r"(sz) : "memory");
}
__device__ __forceinline__ void cp_commit() {
    asm volatile("cp.async.commit_group;" ::: "memory");
}

// ---------------------------------------------------------------------------
// C[z][m][n] = sum_k A[z][m][k]*B[z][n][k]  (+bias,+addsrc,relu,rna)
// amode 0: A row-major; amode 1: implicit im2col 3x3 pad1 over NHWC (H,Wd,CA).
// M % 256 == 0, K % 16 == 0, N arbitrary (tile 128). epi: 1=relu 2=add 4=rna.
// smem: As[ST][BM][RS], Bs[ST][BN][RS] floats (dynamic, 122880 B).
// ---------------------------------------------------------------------------
__global__ void __launch_bounds__(256, 1) gemm_mma(
        const float* __restrict__ A, int lda, long long sAz, int amode,
        int H, int Wd, int CA,
        const float* __restrict__ Bw, long long sBz,
        float* __restrict__ Cc, int ldc, long long sCz,
        const float* __restrict__ bias, long long sBiasz,
        const float* __restrict__ addsrc, long long sAddz,
        int N, int K, int epi) {
    extern __shared__ float sm[];
    float* Asm = sm;                         // ST*BM*RS
    float* Bsm = sm + ST * BM * RS;          // ST*BN*RS
    const uint32_t sA0 = smem_u32(Asm);
    const uint32_t sB0 = smem_u32(Bsm);

    const int tid = threadIdx.x;
    const int wid = tid >> 5, lane = tid & 31;
    const int g = lane >> 2, t4 = lane & 3;
    const int wm = (wid & 3) * 64;           // 4 warps in M
    const int wn = (wid >> 2) * 64;          // 2 warps in N
    const int z = blockIdx.z;
    A  += (size_t)z * sAz;
    Bw += (size_t)z * sBz;
    Cc += (size_t)z * sCz;
    if (bias)   bias   += (size_t)z * sBiasz;
    if (addsrc) addsrc += (size_t)z * sAddz;
    const int m0 = blockIdx.y * BM, n0 = blockIdx.x * BN;
    const int HW = H * Wd;
    const int C = K >> 4;

    const int r0 = tid >> 2;                 // 0..63
    const int c4 = (tid & 3) * 4;            // 0,4,8,12

    auto issue = [&](int c) {
        const int stage = c & (ST - 1);
        const int k0 = c * 16;
        const uint32_t aBase = sA0 + (uint32_t)(stage * BM * RS) * 4;
        const uint32_t bBase = sB0 + (uint32_t)(stage * BN * RS) * 4;
        if (amode == 0) {
#pragma unroll
            for (int h = 0; h < 4; h++) {
                int r = r0 + h * 64;
                cp16(aBase + (uint32_t)(r * RS + c4) * 4,
                     &A[(size_t)(m0 + r) * lda + k0 + c4], 16);
            }
        } else {
            const int kk = k0 / CA;
            const int ky = kk / 3, kx = kk % 3;
            const int ci = k0 % CA + c4;
#pragma unroll
            for (int h = 0; h < 4; h++) {
                int r = r0 + h * 64;
                int m = m0 + r;
                int bimg = m / HW, rem = m % HW;
                int oy = rem / Wd, ox = rem % Wd;
                int iy = oy + ky - 1, ix = ox + kx - 1;
                bool ok = (unsigned)iy < (unsigned)H && (unsigned)ix < (unsigned)Wd;
                const float* src = ok
                    ? &A[(((size_t)bimg * H + iy) * Wd + ix) * CA + ci] : A;
                cp16(aBase + (uint32_t)(r * RS + c4) * 4, src, ok ? 16 : 0);
            }
        }
#pragma unroll
        for (int h = 0; h < 2; h++) {
            int r = r0 + h * 64;
            bool ok = (n0 + r) < N;
            const float* src = ok ? &Bw[(size_t)(n0 + r) * K + k0 + c4] : Bw;
            cp16(bBase + (uint32_t)(r * RS + c4) * 4, src, ok ? 16 : 0);
        }
    };

    float acc[4][8][4];
#pragma unroll
    for (int mi = 0; mi < 4; mi++)
#pragma unroll
        for (int ni = 0; ni < 8; ni++)
#pragma unroll
            for (int q = 0; q < 4; q++) acc[mi][ni][q] = 0.f;

#pragma unroll
    for (int s = 0; s < ST - 1; s++) {
        if (s < C) issue(s);
        cp_commit();
    }

    for (int c = 0; c < C; c++) {
        asm volatile("cp.async.wait_group %0;" :: "n"(ST - 2) : "memory");
        __syncthreads();
        if (c + ST - 1 < C) issue(c + ST - 1);
        cp_commit();

        const int stage = c & (ST - 1);
        const float* Ab = Asm + stage * BM * RS;
        const float* Bb = Bsm + stage * BN * RS;
#pragma unroll
        for (int ks = 0; ks < 2; ks++) {
            const int kb = ks * 8;
            uint32_t afr[4][4], bfr[8][2];
#pragma unroll
            for (int mi = 0; mi < 4; mi++) {
                int m = wm + mi * 16 + g;
                afr[mi][0] = __float_as_uint(Ab[m * RS + kb + t4]);
                afr[mi][1] = __float_as_uint(Ab[(m + 8) * RS + kb + t4]);
                afr[mi][2] = __float_as_uint(Ab[m * RS + kb + t4 + 4]);
                afr[mi][3] = __float_as_uint(Ab[(m + 8) * RS + kb + t4 + 4]);
            }
#pragma unroll
            for (int ni = 0; ni < 8; ni++) {
                int n = wn + ni * 8 + g;
                bfr[ni][0] = __float_as_uint(Bb[n * RS + kb + t4]);
                bfr[ni][1] = __float_as_uint(Bb[n * RS + kb + t4 + 4]);
            }
#pragma unroll
            for (int mi = 0; mi < 4; mi++)
#pragma unroll
                for (int ni = 0; ni < 8; ni++)
                    mma_tf32(acc[mi][ni], afr[mi], bfr[ni]);
        }
        __syncthreads();
    }
    asm volatile("cp.async.wait_group 0;" ::: "memory");

    // ---- epilogue ----
#pragma unroll
    for (int mi = 0; mi < 4; mi++) {
        int row0 = m0 + wm + mi * 16 + g;
#pragma unroll
        for (int ni = 0; ni < 8; ni++) {
            int col = n0 + wn + ni * 8 + 2 * t4;
            if (col >= N) continue;
            float b0 = 0.f, b1 = 0.f;
            if (bias) { b0 = __ldg(&bias[col]); b1 = __ldg(&bias[col + 1]); }
#pragma unroll
            for (int hh = 0; hh < 2; hh++) {
                int row = row0 + hh * 8;
                float v0 = acc[mi][ni][hh * 2 + 0] + b0;
                float v1 = acc[mi][ni][hh * 2 + 1] + b1;
                if (epi & 2) {
                    const float2 a2 = *(const float2*)&addsrc[(size_t)row * ldc + col];
                    v0 += a2.x; v1 += a2.y;
                }
                if (epi & 1) { v0 = fmaxf(v0, 0.f); v1 = fmaxf(v1, 0.f); }
                if (epi & 4) { v0 = rna_tf32(v0); v1 = rna_tf32(v1); }
                *(float2*)&Cc[(size_t)row * ldc + col] = make_float2(v0, v1);
            }
        }
    }
}

// --------------------- prep / small kernels ---------------------------------
__global__ void fold_k(const float* __restrict__ W, const float* __restrict__ b,
                       const float* __restrict__ g, const float* __restrict__ be,
                       const float* __restrict__ m, const float* __restrict__ v,
                       float* __restrict__ Wt, float* __restrict__ bt,
                       int Cin, int Co, int mode) {
    int idx = blockIdx.x * blockDim.x + threadIdx.x;
    int tot = Co * Cin * 9;
    if (idx < tot) {
        int co = idx / (Cin * 9);
        int rem = idx % (Cin * 9);
        int ci = rem / 9, kk = rem % 9;
        float sc = g[co] * rsqrtf(v[co] + 1e-5f);
        float w = W[idx] * sc;
        if (mode) Wt[(size_t)co * (Cin * 9) + kk * Cin + ci] = rna_tf32(w);
        else      Wt[idx] = w;
    }
    if (idx < Co) {
        float sc = g[idx] * rsqrtf(v[idx] + 1e-5f);
        bt[idx] = (b[idx] - m[idx]) * sc + be[idx];
    }
}

__global__ void wat_k(const float* __restrict__ Wa, float* __restrict__ w1,
                      float* __restrict__ w2) {
    long long idx = (long long)blockIdx.x * blockDim.x + threadIdx.x;
    if (idx < 25LL * 600 * 256) {
        int k = (int)(idx % 256); long long t = idx / 256;
        int j = (int)(t % 600);   int n = (int)(t / 600);
        w1[idx] = rna_tf32(Wa[(size_t)n * 201600 + (size_t)(80 + k) * 600 + j]);
    }
    if (idx < 25LL * 600 * 96) {
        int k = (int)(idx % 96); long long t = idx / 96;
        int j = (int)(t % 600);  int n = (int)(t / 600);
        w2[idx] = (k < 80) ? rna_tf32(Wa[(size_t)n * 201600 + (size_t)k * 600 + j]) : 0.f;
    }
}

__global__ void nei_k(int* __restrict__ nei) {
    int i = threadIdx.x;
    if (i >= 25) return;
    const int w = 5, size = 25;
    int n[8]; int c = 0;
    if (i - w >= 0)                           n[c++] = i - w;
    if (i % w != 0)                           n[c++] = i - 1;
    if ((i + 1) % w != 0)                     n[c++] = i + 1;
    if (i + w < size)                         n[c++] = i + w;
    if (i - w - 1 >= 0 && i % w != 0)         n[c++] = i - w - 1;
    if (i - w + 1 >= 0 && (i + 1) % w != 0)   n[c++] = i - w + 1;
    if (i + w - 1 < size && i % w != 0)       n[c++] = i + w - 1;
    if (i + w + 1 < size && (i + 1) % w != 0) n[c++] = i + w + 1;
    while (c < 8) n[c++] = -1;
    for (int j = 0; j < 8; j++) nei[i * 8 + j] = n[j];
}

__global__ void __launch_bounds__(256) conv1_pool_k(
        const float* __restrict__ x, const float* __restrict__ Wf,
        const float* __restrict__ bf, float* __restrict__ out) {
    __shared__ float sx[1200];
    __shared__ float sw[64 * 27];
    __shared__ float sb2[64];
    int b = blockIdx.x;
    int tid = threadIdx.x;
    const float* xb = x + (size_t)b * 1200;
    for (int i = tid; i < 1200; i += 256) sx[i] = xb[i];
    for (int i = tid; i < 64 * 27; i += 256) sw[i] = Wf[i];
    if (tid < 64) sb2[tid] = bf[tid];
    __syncthreads();
    int co = tid & 63, q = tid >> 6;
    float wr[27];
#pragma unroll
    for (int i = 0; i < 27; i++) wr[i] = sw[co * 27 + i];
    float bias = sb2[co];
    for (int p = 0; p < 25; p++) {
        int px = q * 25 + p;
        int oy = px / 10, ox = px % 10;
        float mv = -1e30f;
#pragma unroll
        for (int dy = 0; dy < 3; dy++) {
            int y = 2 * oy - 1 + dy;
            if ((unsigned)y >= 20u) continue;
#pragma unroll
            for (int dx = 0; dx < 3; dx++) {
                int xx = 2 * ox - 1 + dx;
                if ((unsigned)xx >= 20u) continue;
                float s = bias;
#pragma unroll
                for (int ci = 0; ci < 3; ci++)
#pragma unroll
                    for (int ky = 0; ky < 3; ky++) {
                        int iy = y - 1 + ky;
                        if ((unsigned)iy >= 20u) continue;
#pragma unroll
                        for (int kx = 0; kx < 3; kx++) {
                            int ix = xx - 1 + kx;
                            if ((unsigned)ix >= 20u) continue;
                            s += sx[ci * 400 + iy * 20 + ix] * wr[ci * 9 + ky * 3 + kx];
                        }
                    }
                mv = fmaxf(mv, s);
            }
        }
        out[(((size_t)b * 10 + oy) * 10 + ox) * 64 + co] = rna_tf32(fmaxf(mv, 0.f));
    }
}

__global__ void pool_nhwc(const float* __restrict__ in, float* __restrict__ out,
                          int Bt, int HI, int WI, int Ch) {
    int HO = (HI - 1) / 2 + 1;
    long long idx = (long long)blockIdx.x * blockDim.x + threadIdx.x;
    long long total = (long long)Bt * HO * HO * Ch;
    if (idx >= total) return;
    int c = (int)(idx % Ch);
    long long t = idx / Ch;
    int ox = (int)(t % HO); t /= HO;
    int oy = (int)(t % HO);
    long long b = t / HO;
    float mv = -1e30f;
#pragma unroll
    for (int dy = 0; dy < 3; dy++) {
        int y = 2 * oy - 1 + dy;
        if ((unsigned)y >= (unsigned)HI) continue;
#pragma unroll
        for (int dx = 0; dx < 3; dx++) {
            int x2 = 2 * ox - 1 + dx;
            if ((unsigned)x2 >= (unsigned)WI) continue;
            mv = fmaxf(mv, in[(((size_t)b * HI + y) * WI + x2) * Ch + c]);
        }
    }
    out[idx] = mv;
}

__global__ void __launch_bounds__(256) mlp_out_k(
        const float* __restrict__ z, const float* __restrict__ Wb,
        const float* __restrict__ bb, float* __restrict__ out, int Bt) {
    __shared__ float sW[600 * 11];
    __shared__ float sbb[16];
    int n = blockIdx.y;
    const float* wsrc = Wb + (size_t)n * 6000;
    for (int i = threadIdx.x; i < 6000; i += 256)
        sW[(i / 10) * 11 + (i % 10)] = wsrc[i];
    if (threadIdx.x < 10) sbb[threadIdx.x] = bb[n * 10 + threadIdx.x];
    __syncthreads();
    int warp = threadIdx.x >> 5, lane = threadIdx.x & 31;
    for (int it = 0; it < 4; it++) {
        int b = blockIdx.x * 32 + warp * 4 + it;
        const float* zp = z + ((size_t)n * Bt + b) * 600;
        float acc[10];
#pragma unroll
        for (int c = 0; c < 10; c++) acc[c] = 0.f;
        for (int h = lane; h < 600; h += 32) {
            float hv = tanh_fast(zp[h]);
            const float* wr = &sW[h * 11];
#pragma unroll
            for (int c = 0; c < 10; c++) acc[c] += hv * wr[c];
        }
#pragma unroll
        for (int c = 0; c < 10; c++)
#pragma unroll
            for (int o = 16; o > 0; o >>= 1)
                acc[c] += __shfl_xor_sync(0xFFFFFFFFu, acc[c], o);
        float logit[10], mx = -1e30f;
#pragma unroll
        for (int c = 0; c < 10; c++) {
            logit[c] = acc[c] + sbb[c];
            mx = fmaxf(mx, logit[c]);
        }
        float s = 0.f;
#pragma unroll
        for (int c = 0; c < 10; c++) { logit[c] = __expf(logit[c] - mx); s += logit[c]; }
        float inv = 1.f / s;
        if (lane < 10) out[((size_t)n * Bt + b) * 10 + lane] = logit[lane] * inv;
    }
}

__global__ void gather_nb(const float* __restrict__ preds, const int* __restrict__ nei,
                          float* __restrict__ nb, int Bt) {
    long long idx = (long long)blockIdx.x * blockDim.x + threadIdx.x;
    long long total = 25LL * Bt * 96;
    if (idx >= total) return;
    int c = (int)(idx % 96);
    long long t = idx / 96;
    int b = (int)(t % Bt);
    int n = (int)(t / Bt);
    float v = 0.f;
    if (c < 80) {
        int j = c / 10, cc = c % 10;
        int ni = nei[n * 8 + j];
        if (ni >= 0) v = preds[((size_t)ni * Bt + b) * 10 + cc];
    }
    nb[idx] = rna_tf32(v);
}

__global__ void mean_k(const float* __restrict__ second, float* __restrict__ outm, int Bt) {
    int idx = blockIdx.x * blockDim.x + threadIdx.x;
    if (idx >= Bt * 10) return;
    float s = 0.f;
#pragma unroll
    for (int n = 0; n < 25; n++) s += second[(size_t)n * Bt * 10 + idx];
    outm[idx] = s * 0.04f;
}

__global__ void copy_k(const float* __restrict__ src, float* __restrict__ dst, long long n) {
    long long idx = (long long)blockIdx.x * blockDim.x + threadIdx.x;
    if (idx < n) dst[idx] = src[idx];
}

static inline int cdiv(long long a, int b) { return (int)((a + b - 1) / b); }

extern "C" void kernel_launch(void* const* d_in, const int* in_sizes, int n_in,
                              void* d_out, int out_size) {
    const float* x = (const float*)d_in[0];
    const float *Wc[4], *bc[4], *gc[4], *bec[4], *mc[4], *vc[4];
    for (int l = 0; l < 4; l++) {
        int base = 1 + l * 6;
        Wc[l] = (const float*)d_in[base + 0];
        bc[l] = (const float*)d_in[base + 1];
        gc[l] = (const float*)d_in[base + 2];
        bec[l] = (const float*)d_in[base + 3];
        mc[l] = (const float*)d_in[base + 4];
        vc[l] = (const float*)d_in[base + 5];
    }
    const float* Wa = (const float*)d_in[25];
    const float* ba = (const float*)d_in[26];
    const float* Wb = (const float*)d_in[27];
    const float* bb = (const float*)d_in[28];
    int Bt = in_sizes[0] / 1200;

    float *p_pool1, *p_conv2, *p_pool2, *p_conv3, *p_conv4, *p_z1, *p_z2;
    float *p_preds, *p_second, *p_nb, *p_Wat1, *p_Wat2;
    float *p_W1f, *p_b1f, *p_W2f, *p_b2f, *p_W3f, *p_b3f, *p_W4f, *p_b4f;
    int* p_nei;
    cudaGetSymbolAddress((void**)&p_pool1, g_pool1);
    cudaGetSymbolAddress((void**)&p_conv2, g_conv2);
    cudaGetSymbolAddress((void**)&p_pool2, g_pool2);
    cudaGetSymbolAddress((void**)&p_conv3, g_conv3);
    cudaGetSymbolAddress((void**)&p_conv4, g_conv4);
    cudaGetSymbolAddress((void**)&p_z1, g_z1);
    cudaGetSymbolAddress((void**)&p_z2, g_z2);
    cudaGetSymbolAddress((void**)&p_preds, g_preds);
    cudaGetSymbolAddress((void**)&p_second, g_second);
    cudaGetSymbolAddress((void**)&p_nb, g_nb);
    cudaGetSymbolAddress((void**)&p_Wat1, g_Wat1);
    cudaGetSymbolAddress((void**)&p_Wat2, g_Wat2);
    cudaGetSymbolAddress((void**)&p_W1f, g_W1f);
    cudaGetSymbolAddress((void**)&p_b1f, g_b1f);
    cudaGetSymbolAddress((void**)&p_W2f, g_W2f);
    cudaGetSymbolAddress((void**)&p_b2f, g_b2f);
    cudaGetSymbolAddress((void**)&p_W3f, g_W3f);
    cudaGetSymbolAddress((void**)&p_b3f, g_b3f);
    cudaGetSymbolAddress((void**)&p_W4f, g_W4f);
    cudaGetSymbolAddress((void**)&p_b4f, g_b4f);
    cudaGetSymbolAddress((void**)&p_nei, g_nei);

    const int SMEM = ST * (BM + BN) * RS * 4;   // 122880 bytes
    cudaFuncSetAttribute(gemm_mma, cudaFuncAttributeMaxDynamicSharedMemorySize, SMEM);

    fold_k<<<cdiv(64 * 27, 256), 256>>>(Wc[0], bc[0], gc[0], bec[0], mc[0], vc[0], p_W1f, p_b1f, 3, 64, 0);
    fold_k<<<cdiv(128 * 576, 256), 256>>>(Wc[1], bc[1], gc[1], bec[1], mc[1], vc[1], p_W2f, p_b2f, 64, 128, 1);
    fold_k<<<cdiv(256 * 1152, 256), 256>>>(Wc[2], bc[2], gc[2], bec[2], mc[2], vc[2], p_W3f, p_b3f, 128, 256, 1);
    fold_k<<<cdiv(256 * 2304, 256), 256>>>(Wc[3], bc[3], gc[3], bec[3], mc[3], vc[3], p_W4f, p_b4f, 256, 256, 1);
    wat_k<<<cdiv(25LL * 600 * 256, 256), 256>>>(Wa, p_Wat1, p_Wat2);
    nei_k<<<1, 32>>>(p_nei);

    conv1_pool_k<<<Bt, 256>>>(x, p_W1f, p_b1f, p_pool1);

    long long rows2 = (long long)Bt * 100;
    long long rows3 = (long long)Bt * 25;

    // conv2: implicit GEMM, K=576, N=128
    gemm_mma<<<dim3(1, (unsigned)(rows2 / BM), 1), 256, SMEM>>>(
        p_pool1, 0, 0, 1, 10, 10, 64,
        p_W2f, 0, p_conv2, 128, 0,
        p_b2f, 0, nullptr, 0, 128, 576, 1 | 4);

    pool_nhwc<<<cdiv((long long)Bt * 25 * 128, 256), 256>>>(p_conv2, p_pool2, Bt, 10, 10, 128);

    // conv3: K=1152, N=256
    gemm_mma<<<dim3(2, (unsigned)(rows3 / BM), 1), 256, SMEM>>>(
        p_pool2, 0, 0, 1, 5, 5, 128,
        p_W3f, 0, p_conv3, 256, 0,
        p_b3f, 0, nullptr, 0, 256, 1152, 1 | 4);

    // conv4: K=2304, N=256
    gemm_mma<<<dim3(2, (unsigned)(rows3 / BM), 1), 256, SMEM>>>(
        p_conv3, 0, 0, 1, 5, 5, 256,
        p_W4f, 0, p_conv4, 256, 0,
        p_b4f, 0, nullptr, 0, 256, 2304, 1 | 4);

    // stage1: K=256, N=600
    gemm_mma<<<dim3(5, (unsigned)(Bt / BM), 25), 256, SMEM>>>(
        p_conv4, 25 * 256, 256, 0, 0, 0, 0,
        p_Wat1, 600LL * 256, p_z1, 600, (long long)Bt * 600,
        ba, 600, nullptr, 0, 600, 256, 0);

    mlp_out_k<<<dim3(Bt / 32, 25), 256>>>(p_z1, Wb, bb, p_preds, Bt);

    gather_nb<<<cdiv(25LL * Bt * 96, 256), 256>>>(p_preds, p_nei, p_nb, Bt);

    // stage2: K=96, N=600, z2 = z1 + nb@Wat2
    gemm_mma<<<dim3(5, (unsigned)(Bt / BM), 25), 256, SMEM>>>(
        p_nb, 96, (long long)Bt * 96, 0, 0, 0, 0,
        p_Wat2, 600LL * 96, p_z2, 600, (long long)Bt * 600,
        nullptr, 0, p_z1, (long long)Bt * 600, 600, 96, 2);

    mlp_out_k<<<dim3(Bt / 32, 25), 256>>>(p_z2, Wb, bb, p_second, Bt);

    float* outF = (float*)d_out;
    mean_k<<<cdiv(Bt * 10, 256), 256>>>(p_second, outF, Bt);
    long long secN = 25LL * Bt * 10;
    long long room = (long long)out_size - (long long)Bt * 10;
    if (room > 0) {
        long long ncopy = room < secN ? room : secN;
        copy_k<<<cdiv(ncopy, 256), 256>>>(p_second, outF + (size_t)Bt * 10, ncopy);
    }
}